// round 1
// baseline (speedup 1.0000x reference)
#include <cuda_runtime.h>
#include <math.h>

#define NFEAT  128
#define HIDF   128
#define HEADS  4
#define NHID   32
#define NCLASS 40
#define NEGS   0.2f
#define EPSBN  1e-5f
#define MAXN   100000
#define MAXET  1700000   // E (1.6M) + N (100K) self-loops

// ---------------- scratch (static device globals; no allocation) ----------------
__device__ float    g_h   [(size_t)MAXN * HIDF];   // projected features (also reused as h2 [N,40])
__device__ float    g_agg [(size_t)MAXN * HIDF];   // aggregation output / next-layer input
__device__ float    g_als [(size_t)MAXN * HEADS];
__device__ float    g_ald [(size_t)MAXN * HEADS];
__device__ unsigned g_gmax[(size_t)MAXN * HEADS];  // encoded segment max
__device__ float    g_ssum[(size_t)MAXN * HEADS];
__device__ float    g_ex  [(size_t)MAXET * HEADS]; // exp(e - max) per edge

// order-preserving float<->uint encoding (monotone increasing)
__device__ __forceinline__ unsigned fenc(float f) {
    unsigned u = __float_as_uint(f);
    return (u & 0x80000000u) ? ~u : (u | 0x80000000u);
}
__device__ __forceinline__ float fdec(unsigned u) {
    return (u & 0x80000000u) ? __uint_as_float(u ^ 0x80000000u) : __uint_as_float(~u);
}
__device__ __forceinline__ float lrelu(float e) { return e > 0.f ? e : NEGS * e; }

// ---------------- zero fill ----------------
__global__ void zk(float* __restrict__ p, long cnt) {
    long i = (long)blockIdx.x * blockDim.x + threadIdx.x;
    long stride = (long)gridDim.x * blockDim.x;
    for (; i < cnt; i += stride) p[i] = 0.f;
}

// ---------------- GEMM: O[n][128] = X[n][128] @ W[128][128]^T ----------------
// 128-row x 128-col tile per block, 256 threads, 8x8 accumulators per thread.
__global__ void gemm128(const float* __restrict__ X, const float* __restrict__ W,
                        float* __restrict__ O, int n) {
    __shared__ float As[32][132];   // As[kk][row]
    __shared__ float Bs[32][132];   // Bs[kk][col]
    int t  = threadIdx.x;
    int tx = t & 15;                // col group (8 cols)
    int ty = t >> 4;                // row group (8 rows)
    int row0 = blockIdx.x * 128;

    float acc[8][8];
#pragma unroll
    for (int i = 0; i < 8; i++)
#pragma unroll
        for (int j = 0; j < 8; j++) acc[i][j] = 0.f;

    for (int kt = 0; kt < 128; kt += 32) {
#pragma unroll
        for (int i = 0; i < 16; i++) {
            int idx = t + 256 * i;          // 0..4095
            int r  = idx >> 5;              // 0..127
            int kk = idx & 31;
            int gr = row0 + r;
            As[kk][r] = (gr < n) ? X[(size_t)gr * 128 + kt + kk] : 0.f;
            Bs[kk][r] = W[(size_t)r * 128 + kt + kk];   // r = output col here
        }
        __syncthreads();
#pragma unroll
        for (int kk = 0; kk < 32; kk++) {
            float4 a0 = *(const float4*)&As[kk][ty * 8];
            float4 a1 = *(const float4*)&As[kk][ty * 8 + 4];
            float4 b0 = *(const float4*)&Bs[kk][tx * 8];
            float4 b1 = *(const float4*)&Bs[kk][tx * 8 + 4];
            float av[8] = {a0.x, a0.y, a0.z, a0.w, a1.x, a1.y, a1.z, a1.w};
            float bv[8] = {b0.x, b0.y, b0.z, b0.w, b1.x, b1.y, b1.z, b1.w};
#pragma unroll
            for (int i = 0; i < 8; i++)
#pragma unroll
                for (int j = 0; j < 8; j++) acc[i][j] += av[i] * bv[j];
        }
        __syncthreads();
    }
#pragma unroll
    for (int i = 0; i < 8; i++) {
        int gr = row0 + ty * 8 + i;
        if (gr < n) {
            float4 o0 = make_float4(acc[i][0], acc[i][1], acc[i][2], acc[i][3]);
            float4 o1 = make_float4(acc[i][4], acc[i][5], acc[i][6], acc[i][7]);
            float4* dst = (float4*)(O + (size_t)gr * 128 + tx * 8);
            dst[0] = o0; dst[1] = o1;
        }
    }
}

// ---------------- attention logits: als/ald [n][4] from h [n][128] ----------------
__global__ void alkern(const float* __restrict__ h, const float* __restrict__ as,
                       const float* __restrict__ ad, float* __restrict__ als,
                       float* __restrict__ ald, int n) {
    int lane = threadIdx.x & 31;
    int node = (blockIdx.x * blockDim.x + threadIdx.x) >> 5;
    if (node >= n) return;
    float4 v = ((const float4*)(h + (size_t)node * 128))[lane];
    float4 a = ((const float4*)as)[lane];
    float4 b = ((const float4*)ad)[lane];
    float ps = v.x * a.x + v.y * a.y + v.z * a.z + v.w * a.w;
    float pd = v.x * b.x + v.y * b.y + v.z * b.z + v.w * b.w;
#pragma unroll
    for (int off = 1; off <= 4; off <<= 1) {
        ps += __shfl_xor_sync(0xffffffffu, ps, off);
        pd += __shfl_xor_sync(0xffffffffu, pd, off);
    }
    if ((lane & 7) == 0) {
        int head = lane >> 3;
        als[node * 4 + head] = ps;
        ald[node * 4 + head] = pd;
    }
}

// ---------------- edge pass A: segment max ----------------
__global__ void passA(const int* __restrict__ src, const int* __restrict__ dst,
                      const float* __restrict__ als, const float* __restrict__ ald,
                      unsigned* __restrict__ gmax, int E, int ET) {
    int i = blockIdx.x * blockDim.x + threadIdx.x;
    int stride = gridDim.x * blockDim.x;
    for (; i < ET; i += stride) {
        int s, d;
        if (i < E) { s = src[i]; d = dst[i]; } else { s = d = i - E; }
        float4 a = ((const float4*)als)[s];
        float4 b = ((const float4*)ald)[d];
        float e0 = lrelu(a.x + b.x), e1 = lrelu(a.y + b.y);
        float e2 = lrelu(a.z + b.z), e3 = lrelu(a.w + b.w);
        unsigned* gm = gmax + (size_t)d * 4;
        atomicMax(gm + 0, fenc(e0));
        atomicMax(gm + 1, fenc(e1));
        atomicMax(gm + 2, fenc(e2));
        atomicMax(gm + 3, fenc(e3));
    }
}

// ---------------- edge pass B: exp + segment sum ----------------
__global__ void passB(const int* __restrict__ src, const int* __restrict__ dst,
                      const float* __restrict__ als, const float* __restrict__ ald,
                      const unsigned* __restrict__ gmax, float* __restrict__ ssum,
                      float* __restrict__ ex, int E, int ET) {
    int i = blockIdx.x * blockDim.x + threadIdx.x;
    int stride = gridDim.x * blockDim.x;
    for (; i < ET; i += stride) {
        int s, d;
        if (i < E) { s = src[i]; d = dst[i]; } else { s = d = i - E; }
        float4 a = ((const float4*)als)[s];
        float4 b = ((const float4*)ald)[d];
        const unsigned* gm = gmax + (size_t)d * 4;
        float x0 = __expf(lrelu(a.x + b.x) - fdec(gm[0]));
        float x1 = __expf(lrelu(a.y + b.y) - fdec(gm[1]));
        float x2 = __expf(lrelu(a.z + b.z) - fdec(gm[2]));
        float x3 = __expf(lrelu(a.w + b.w) - fdec(gm[3]));
        ((float4*)ex)[i] = make_float4(x0, x1, x2, x3);
        float* ss = ssum + (size_t)d * 4;
        atomicAdd(ss + 0, x0);
        atomicAdd(ss + 1, x1);
        atomicAdd(ss + 2, x2);
        atomicAdd(ss + 3, x3);
    }
}

// ---------------- edge pass C: weighted scatter (warp per edge, 128 cols) ----------------
__global__ void passC(const int* __restrict__ src, const int* __restrict__ dst,
                      const float* __restrict__ h, const float* __restrict__ ex,
                      const float* __restrict__ ssum, float* __restrict__ agg,
                      int E, int ET) {
    int lane = threadIdx.x & 31;
    int w = (blockIdx.x * blockDim.x + threadIdx.x) >> 5;
    int nw = (gridDim.x * blockDim.x) >> 5;
    for (int i = w; i < ET; i += nw) {
        int s, d;
        if (i < E) { s = src[i]; d = dst[i]; } else { s = d = i - E; }
        int head = lane >> 3;
        float alpha = ex[(size_t)i * 4 + head] / ssum[(size_t)d * 4 + head];
        float4 hv = ((const float4*)h)[(size_t)s * 32 + lane];
        float* out = agg + (size_t)d * 128 + lane * 4;
        atomicAdd(out + 0, alpha * hv.x);
        atomicAdd(out + 1, alpha * hv.y);
        atomicAdd(out + 2, alpha * hv.z);
        atomicAdd(out + 3, alpha * hv.w);
    }
}

// ---------------- bias + BN(eval) + ReLU, in place ----------------
__global__ void bnrelu(float* __restrict__ x, const float* __restrict__ bias,
                       const float* __restrict__ g, const float* __restrict__ be,
                       const float* __restrict__ m, const float* __restrict__ v, int n) {
    long i = (long)blockIdx.x * blockDim.x + threadIdx.x;
    long total = (long)n * 128;
    long stride = (long)gridDim.x * blockDim.x;
    for (; i < total; i += stride) {
        int c = (int)(i & 127);
        float val = x[i] + bias[c];
        val = (val - m[c]) * rsqrtf(v[c] + EPSBN) * g[c] + be[c];
        x[i] = val > 0.f ? val : 0.f;
    }
}

// ---------------- layer-2 GEMM (128 -> 40) fused with attention logits ----------------
__global__ void gemm40(const float* __restrict__ X, const float* __restrict__ W,
                       const float* __restrict__ as2, const float* __restrict__ ad2,
                       float* __restrict__ H2, float* __restrict__ als,
                       float* __restrict__ ald, int n) {
    __shared__ float Ws[NCLASS][129];
    __shared__ float asS[NCLASS], adS[NCLASS];
    __shared__ float xs[8][128];
    int t = threadIdx.x;
    for (int i = t; i < NCLASS * 128; i += blockDim.x) {
        int c = i >> 7, k = i & 127;
        Ws[c][k] = W[i];
    }
    if (t < NCLASS) { asS[t] = as2[t]; adS[t] = ad2[t]; }
    __syncthreads();

    int wid = t >> 5, lane = t & 31;
    int wtotal = (gridDim.x * blockDim.x) >> 5;
    for (int row = blockIdx.x * 8 + wid; row < n; row += wtotal) {
        float4 xv = ((const float4*)(X + (size_t)row * 128))[lane];
        ((float4*)xs[wid])[lane] = xv;
        __syncwarp();
        float acc0 = 0.f, acc1 = 0.f;
        int c0 = lane, c1 = 32 + lane;
#pragma unroll 8
        for (int k = 0; k < 128; k++) {
            float xk = xs[wid][k];
            acc0 += xk * Ws[c0][k];
            if (lane < 8) acc1 += xk * Ws[c1][k];
        }
        H2[(size_t)row * NCLASS + c0] = acc0;
        if (lane < 8) H2[(size_t)row * NCLASS + c1] = acc1;
        float ps = acc0 * asS[c0] + (lane < 8 ? acc1 * asS[c1] : 0.f);
        float pd = acc0 * adS[c0] + (lane < 8 ? acc1 * adS[c1] : 0.f);
#pragma unroll
        for (int off = 16; off >= 1; off >>= 1) {
            ps += __shfl_xor_sync(0xffffffffu, ps, off);
            pd += __shfl_xor_sync(0xffffffffu, pd, off);
        }
        if (lane == 0) { als[row] = ps; ald[row] = pd; }
        __syncwarp();
    }
}

// ---------------- layer-2 edge passes (1 head) ----------------
__global__ void passA2(const int* __restrict__ src, const int* __restrict__ dst,
                       const float* __restrict__ als, const float* __restrict__ ald,
                       unsigned* __restrict__ gmax, int E, int ET) {
    int i = blockIdx.x * blockDim.x + threadIdx.x;
    int stride = gridDim.x * blockDim.x;
    for (; i < ET; i += stride) {
        int s, d;
        if (i < E) { s = src[i]; d = dst[i]; } else { s = d = i - E; }
        atomicMax(&gmax[d], fenc(lrelu(als[s] + ald[d])));
    }
}

__global__ void passB2(const int* __restrict__ src, const int* __restrict__ dst,
                       const float* __restrict__ als, const float* __restrict__ ald,
                       const unsigned* __restrict__ gmax, float* __restrict__ ssum,
                       float* __restrict__ ex, int E, int ET) {
    int i = blockIdx.x * blockDim.x + threadIdx.x;
    int stride = gridDim.x * blockDim.x;
    for (; i < ET; i += stride) {
        int s, d;
        if (i < E) { s = src[i]; d = dst[i]; } else { s = d = i - E; }
        float xv = __expf(lrelu(als[s] + ald[d]) - fdec(gmax[d]));
        ex[i] = xv;
        atomicAdd(&ssum[d], xv);
    }
}

__global__ void passC2(const int* __restrict__ src, const int* __restrict__ dst,
                       const float* __restrict__ h2, const float* __restrict__ ex,
                       const float* __restrict__ ssum, float* __restrict__ agg,
                       int E, int ET) {
    int lane = threadIdx.x & 31;
    int w = (blockIdx.x * blockDim.x + threadIdx.x) >> 5;
    int nw = (gridDim.x * blockDim.x) >> 5;
    for (int i = w; i < ET; i += nw) {
        int s, d;
        if (i < E) { s = src[i]; d = dst[i]; } else { s = d = i - E; }
        float alpha = ex[i] / ssum[d];
        for (int c = lane; c < NCLASS; c += 32)
            atomicAdd(&agg[(size_t)d * NCLASS + c], alpha * h2[(size_t)s * NCLASS + c]);
    }
}

// ---------------- bias + log_softmax over 40 classes (warp per node) ----------------
__global__ void lsm(const float* __restrict__ agg, const float* __restrict__ b2,
                    float* __restrict__ out, int n) {
    int lane = threadIdx.x & 31;
    int node = (blockIdx.x * blockDim.x + threadIdx.x) >> 5;
    if (node >= n) return;
    const float* row = agg + (size_t)node * NCLASS;
    float x0 = row[lane] + b2[lane];
    float x1 = (lane < 8) ? row[32 + lane] + b2[32 + lane] : -3.4e38f;
    float mx = fmaxf(x0, x1);
#pragma unroll
    for (int off = 16; off >= 1; off >>= 1)
        mx = fmaxf(mx, __shfl_xor_sync(0xffffffffu, mx, off));
    float s = __expf(x0 - mx) + (lane < 8 ? __expf(x1 - mx) : 0.f);
#pragma unroll
    for (int off = 16; off >= 1; off >>= 1)
        s += __shfl_xor_sync(0xffffffffu, s, off);
    float lse = logf(s);
    float* orow = out + (size_t)node * NCLASS;
    orow[lane] = x0 - mx - lse;
    if (lane < 8) orow[32 + lane] = x1 - mx - lse;
}

// ---------------- host ----------------
extern "C" void kernel_launch(void* const* d_in, const int* in_sizes, int n_in,
                              void* d_out, int out_size) {
    const float* x   = (const float*)d_in[0];
    const int*   ei  = (const int*)d_in[1];
    const float* W0  = (const float*)d_in[2];
    const float* as0 = (const float*)d_in[3];
    const float* ad0 = (const float*)d_in[4];
    const float* b0  = (const float*)d_in[5];
    const float* g0  = (const float*)d_in[6];
    const float* be0 = (const float*)d_in[7];
    const float* m0  = (const float*)d_in[8];
    const float* v0  = (const float*)d_in[9];
    const float* W1  = (const float*)d_in[10];
    const float* as1 = (const float*)d_in[11];
    const float* ad1 = (const float*)d_in[12];
    const float* b1  = (const float*)d_in[13];
    const float* g1  = (const float*)d_in[14];
    const float* be1 = (const float*)d_in[15];
    const float* m1  = (const float*)d_in[16];
    const float* v1  = (const float*)d_in[17];
    const float* W2  = (const float*)d_in[18];
    const float* as2 = (const float*)d_in[19];
    const float* ad2 = (const float*)d_in[20];
    const float* b2  = (const float*)d_in[21];

    int n  = in_sizes[0] / NFEAT;
    int E  = in_sizes[1] / 2;
    int ET = E + n;

    float *h, *agg, *als, *ald, *ssum, *ex;
    unsigned* gmax;
    cudaGetSymbolAddress((void**)&h, g_h);
    cudaGetSymbolAddress((void**)&agg, g_agg);
    cudaGetSymbolAddress((void**)&als, g_als);
    cudaGetSymbolAddress((void**)&ald, g_ald);
    cudaGetSymbolAddress((void**)&gmax, g_gmax);
    cudaGetSymbolAddress((void**)&ssum, g_ssum);
    cudaGetSymbolAddress((void**)&ex, g_ex);

    const int gb = (n + 127) / 128;          // gemm blocks
    const int ab = (n + 7) / 8;              // warp-per-node blocks
    const int eb = (ET + 255) / 256;         // thread-per-edge blocks
    const int wb = (ET + 7) / 8;             // warp-per-edge blocks
    const int zb4 = ((long)n * 4 + 255) / 256;
    const int zbH = (int)(((long)n * 128 + 255) / 256);
    const int zbC = (int)(((long)n * NCLASS + 255) / 256);

    // ---------------- layer 0 ----------------
    gemm128<<<gb, 256>>>(x, W0, h, n);
    alkern<<<ab, 256>>>(h, as0, ad0, als, ald, n);
    zk<<<zb4, 256>>>((float*)gmax, (long)n * 4);
    zk<<<zb4, 256>>>(ssum, (long)n * 4);
    zk<<<zbH, 256>>>(agg, (long)n * 128);
    passA<<<eb, 256>>>(ei, ei + E, als, ald, gmax, E, ET);
    passB<<<eb, 256>>>(ei, ei + E, als, ald, gmax, ssum, ex, E, ET);
    passC<<<wb, 256>>>(ei, ei + E, h, ex, ssum, agg, E, ET);
    bnrelu<<<zbH, 256>>>(agg, b0, g0, be0, m0, v0, n);

    // ---------------- layer 1 ----------------
    gemm128<<<gb, 256>>>(agg, W1, h, n);
    alkern<<<ab, 256>>>(h, as1, ad1, als, ald, n);
    zk<<<zb4, 256>>>((float*)gmax, (long)n * 4);
    zk<<<zb4, 256>>>(ssum, (long)n * 4);
    // NOTE: agg is the gemm input but gemm128 already consumed it (stream order)
    zk<<<zbH, 256>>>(agg, (long)n * 128);
    passA<<<eb, 256>>>(ei, ei + E, als, ald, gmax, E, ET);
    passB<<<eb, 256>>>(ei, ei + E, als, ald, gmax, ssum, ex, E, ET);
    passC<<<wb, 256>>>(ei, ei + E, h, ex, ssum, agg, E, ET);
    bnrelu<<<zbH, 256>>>(agg, b1, g1, be1, m1, v1, n);

    // ---------------- layer 2 (heads=1, 40 classes) ----------------
    gemm40<<<1184, 256>>>(agg, W2, as2, ad2, h, als, ald, n);
    zk<<<(n + 255) / 256, 256>>>((float*)gmax, (long)n);
    zk<<<(n + 255) / 256, 256>>>(ssum, (long)n);
    zk<<<zbC, 256>>>(agg, (long)n * NCLASS);
    passA2<<<eb, 256>>>(ei, ei + E, als, ald, gmax, E, ET);
    passB2<<<eb, 256>>>(ei, ei + E, als, ald, gmax, ssum, ex, E, ET);
    passC2<<<wb, 256>>>(ei, ei + E, h, ex, ssum, agg, E, ET);
    lsm<<<ab, 256>>>(agg, b2, (float*)d_out, n);
}

// round 2
// speedup vs baseline: 2.3515x; 2.3515x over previous
#include <cuda_runtime.h>
#include <math.h>

#define NFEAT  128
#define HIDF   128
#define HEADS  4
#define NHID   32
#define NCLASS 40
#define NEGS   0.2f
#define EPSBN  1e-5f
#define MAXN   100000
#define MAXET  1700000   // E (1.6M) + N (100K) self-loops
#define SBS    1024

// ---------------- scratch (static device globals; no allocation) ----------------
__device__ float g_h   [(size_t)MAXN * HIDF];   // projected features (reused as h2 [N,40])
__device__ float g_agg [(size_t)MAXN * HIDF];   // aggregation output / next-layer input
__device__ float g_als [(size_t)MAXN * HEADS];
__device__ float g_ald [(size_t)MAXN * HEADS];
__device__ int   g_rowptr[MAXN + 1];
__device__ int   g_cnt   [MAXN];
__device__ int   g_bsum  [SBS];
__device__ int   g_csrsrc[MAXET];

__device__ __forceinline__ float lrelu(float e) { return e > 0.f ? e : NEGS * e; }

__device__ __forceinline__ float wredmax(float v) {
#pragma unroll
    for (int o = 16; o >= 1; o >>= 1) v = fmaxf(v, __shfl_xor_sync(0xffffffffu, v, o));
    return v;
}
__device__ __forceinline__ float wredsum(float v) {
#pragma unroll
    for (int o = 16; o >= 1; o >>= 1) v += __shfl_xor_sync(0xffffffffu, v, o);
    return v;
}

// ---------------- zero fill (ints) ----------------
__global__ void zki(int* __restrict__ p, int cnt) {
    int i = blockIdx.x * blockDim.x + threadIdx.x;
    int stride = gridDim.x * blockDim.x;
    for (; i < cnt; i += stride) p[i] = 0;
}

// ---------------- CSR build ----------------
__global__ void histK(const int* __restrict__ dst, int* __restrict__ hist, int E, int ET) {
    int i = blockIdx.x * blockDim.x + threadIdx.x;
    int stride = gridDim.x * blockDim.x;
    for (; i < ET; i += stride) {
        int d = (i < E) ? dst[i] : (i - E);
        atomicAdd(&hist[d], 1);
    }
}

__global__ void scan1(const int* __restrict__ hist, int* __restrict__ rowptr,
                      int* __restrict__ bsum, int n) {
    __shared__ int tmp[SBS];
    int tid = threadIdx.x;
    int i = blockIdx.x * SBS + tid;
    int val = (i < n) ? hist[i] : 0;
    tmp[tid] = val;
    __syncthreads();
#pragma unroll
    for (int off = 1; off < SBS; off <<= 1) {
        int t2 = (tid >= off) ? tmp[tid - off] : 0;
        __syncthreads();
        tmp[tid] += t2;
        __syncthreads();
    }
    if (i < n) rowptr[i + 1] = tmp[tid];
    if (tid == SBS - 1) bsum[blockIdx.x] = tmp[SBS - 1];
    if (i == 0) rowptr[0] = 0;
}

__global__ void scan2(int* __restrict__ bsum, int nb) {
    __shared__ int tmp[SBS];
    int tid = threadIdx.x;
    int v = (tid < nb) ? bsum[tid] : 0;
    tmp[tid] = v;
    __syncthreads();
#pragma unroll
    for (int off = 1; off < SBS; off <<= 1) {
        int t2 = (tid >= off) ? tmp[tid - off] : 0;
        __syncthreads();
        tmp[tid] += t2;
        __syncthreads();
    }
    if (tid < nb) bsum[tid] = tmp[tid] - v;   // exclusive
}

__global__ void scan3(int* __restrict__ rowptr, const int* __restrict__ bsum, int n) {
    int tid = threadIdx.x;
    int i = blockIdx.x * SBS + tid;
    if (i < n) rowptr[i + 1] += bsum[blockIdx.x];
}

__global__ void scatterK(const int* __restrict__ src, const int* __restrict__ dst,
                         const int* __restrict__ rowptr, int* __restrict__ cnt,
                         int* __restrict__ csrsrc, int E, int ET) {
    int i = blockIdx.x * blockDim.x + threadIdx.x;
    int stride = gridDim.x * blockDim.x;
    for (; i < ET; i += stride) {
        int s, d;
        if (i < E) { s = src[i]; d = dst[i]; } else { s = d = i - E; }
        int pos = rowptr[d] + atomicAdd(&cnt[d], 1);
        csrsrc[pos] = s;
    }
}

// ---------------- GEMM: O[n][128] = X[n][128] @ W[128][128]^T ----------------
__global__ void gemm128(const float* __restrict__ X, const float* __restrict__ W,
                        float* __restrict__ O, int n) {
    __shared__ float As[32][132];
    __shared__ float Bs[32][132];
    int t  = threadIdx.x;
    int tx = t & 15;
    int ty = t >> 4;
    int row0 = blockIdx.x * 128;

    float acc[8][8];
#pragma unroll
    for (int i = 0; i < 8; i++)
#pragma unroll
        for (int j = 0; j < 8; j++) acc[i][j] = 0.f;

    for (int kt = 0; kt < 128; kt += 32) {
#pragma unroll
        for (int i = 0; i < 16; i++) {
            int idx = t + 256 * i;
            int r  = idx >> 5;
            int kk = idx & 31;
            int gr = row0 + r;
            As[kk][r] = (gr < n) ? X[(size_t)gr * 128 + kt + kk] : 0.f;
            Bs[kk][r] = W[(size_t)r * 128 + kt + kk];
        }
        __syncthreads();
#pragma unroll
        for (int kk = 0; kk < 32; kk++) {
            float4 a0 = *(const float4*)&As[kk][ty * 8];
            float4 a1 = *(const float4*)&As[kk][ty * 8 + 4];
            float4 b0 = *(const float4*)&Bs[kk][tx * 8];
            float4 b1 = *(const float4*)&Bs[kk][tx * 8 + 4];
            float av[8] = {a0.x, a0.y, a0.z, a0.w, a1.x, a1.y, a1.z, a1.w};
            float bv[8] = {b0.x, b0.y, b0.z, b0.w, b1.x, b1.y, b1.z, b1.w};
#pragma unroll
            for (int i = 0; i < 8; i++)
#pragma unroll
                for (int j = 0; j < 8; j++) acc[i][j] += av[i] * bv[j];
        }
        __syncthreads();
    }
#pragma unroll
    for (int i = 0; i < 8; i++) {
        int gr = row0 + ty * 8 + i;
        if (gr < n) {
            float4 o0 = make_float4(acc[i][0], acc[i][1], acc[i][2], acc[i][3]);
            float4 o1 = make_float4(acc[i][4], acc[i][5], acc[i][6], acc[i][7]);
            float4* dst = (float4*)(O + (size_t)gr * 128 + tx * 8);
            dst[0] = o0; dst[1] = o1;
        }
    }
}

// ---------------- attention logits: als/ald [n][4] from h [n][128] ----------------
__global__ void alkern(const float* __restrict__ h, const float* __restrict__ as,
                       const float* __restrict__ ad, float* __restrict__ als,
                       float* __restrict__ ald, int n) {
    int lane = threadIdx.x & 31;
    int node = (blockIdx.x * blockDim.x + threadIdx.x) >> 5;
    if (node >= n) return;
    float4 v = ((const float4*)(h + (size_t)node * 128))[lane];
    float4 a = ((const float4*)as)[lane];
    float4 b = ((const float4*)ad)[lane];
    float ps = v.x * a.x + v.y * a.y + v.z * a.z + v.w * a.w;
    float pd = v.x * b.x + v.y * b.y + v.z * b.z + v.w * b.w;
#pragma unroll
    for (int off = 1; off <= 4; off <<= 1) {
        ps += __shfl_xor_sync(0xffffffffu, ps, off);
        pd += __shfl_xor_sync(0xffffffffu, pd, off);
    }
    if ((lane & 7) == 0) {
        int head = lane >> 3;
        als[node * 4 + head] = ps;
        ald[node * 4 + head] = pd;
    }
}

// ---------------- fused GAT edge stage, 4 heads: max + softmax + gather + bias/BN/ReLU ----------------
__global__ void gat_edge4(const int* __restrict__ rowptr, const int* __restrict__ csrsrc,
                          const float* __restrict__ als, const float* __restrict__ ald,
                          const float* __restrict__ h, float* __restrict__ out,
                          const float* __restrict__ bias, const float* __restrict__ gam,
                          const float* __restrict__ bet, const float* __restrict__ mu,
                          const float* __restrict__ var, int n) {
    int lane = threadIdx.x & 31;
    int d = (blockIdx.x * blockDim.x + threadIdx.x) >> 5;
    if (d >= n) return;

    int start = rowptr[d], end = rowptr[d + 1];
    float4 bld = ((const float4*)ald)[d];

    // phase 1: segment max per head
    float m0 = -3.4e38f, m1 = -3.4e38f, m2 = -3.4e38f, m3 = -3.4e38f;
    for (int e = start + lane; e < end; e += 32) {
        int s = csrsrc[e];
        float4 a = ((const float4*)als)[s];
        m0 = fmaxf(m0, lrelu(a.x + bld.x));
        m1 = fmaxf(m1, lrelu(a.y + bld.y));
        m2 = fmaxf(m2, lrelu(a.z + bld.z));
        m3 = fmaxf(m3, lrelu(a.w + bld.w));
    }
    m0 = wredmax(m0); m1 = wredmax(m1); m2 = wredmax(m2); m3 = wredmax(m3);

    // phase 2: exp-sum per head
    float s0 = 0.f, s1 = 0.f, s2 = 0.f, s3 = 0.f;
    for (int e = start + lane; e < end; e += 32) {
        int s = csrsrc[e];
        float4 a = ((const float4*)als)[s];
        s0 += __expf(lrelu(a.x + bld.x) - m0);
        s1 += __expf(lrelu(a.y + bld.y) - m1);
        s2 += __expf(lrelu(a.z + bld.z) - m2);
        s3 += __expf(lrelu(a.w + bld.w) - m3);
    }
    s0 = wredsum(s0); s1 = wredsum(s1); s2 = wredsum(s2); s3 = wredsum(s3);
    float i0 = __frcp_rn(s0), i1 = __frcp_rn(s1), i2 = __frcp_rn(s2), i3 = __frcp_rn(s3);

    // phase 3: weighted gather. lane owns columns [4*lane, 4*lane+4); head = lane>>3
    int head = lane >> 3;
    float4 acc = make_float4(0.f, 0.f, 0.f, 0.f);
    for (int base = start; base < end; base += 32) {
        int e = base + lane;
        int sv = 0;
        float a0 = 0.f, a1 = 0.f, a2 = 0.f, a3 = 0.f;
        if (e < end) {
            sv = csrsrc[e];
            float4 a = ((const float4*)als)[sv];
            a0 = __expf(lrelu(a.x + bld.x) - m0) * i0;
            a1 = __expf(lrelu(a.y + bld.y) - m1) * i1;
            a2 = __expf(lrelu(a.z + bld.z) - m2) * i2;
            a3 = __expf(lrelu(a.w + bld.w) - m3) * i3;
        }
        int cnt = min(32, end - base);
        for (int j = 0; j < cnt; j++) {
            int   sj = __shfl_sync(0xffffffffu, sv, j);
            float b0 = __shfl_sync(0xffffffffu, a0, j);
            float b1 = __shfl_sync(0xffffffffu, a1, j);
            float b2 = __shfl_sync(0xffffffffu, a2, j);
            float b3 = __shfl_sync(0xffffffffu, a3, j);
            float aj = (head == 0) ? b0 : (head == 1) ? b1 : (head == 2) ? b2 : b3;
            float4 hv = ((const float4*)h)[(size_t)sj * 32 + lane];
            acc.x += aj * hv.x; acc.y += aj * hv.y;
            acc.z += aj * hv.z; acc.w += aj * hv.w;
        }
    }

    // epilogue: +bias, BN(eval), ReLU
    float4 bb = ((const float4*)bias)[lane];
    float4 gg = ((const float4*)gam)[lane];
    float4 be = ((const float4*)bet)[lane];
    float4 mm = ((const float4*)mu)[lane];
    float4 vv = ((const float4*)var)[lane];
    float4 o;
    o.x = (acc.x + bb.x - mm.x) * rsqrtf(vv.x + EPSBN) * gg.x + be.x;
    o.y = (acc.y + bb.y - mm.y) * rsqrtf(vv.y + EPSBN) * gg.y + be.y;
    o.z = (acc.z + bb.z - mm.z) * rsqrtf(vv.z + EPSBN) * gg.z + be.z;
    o.w = (acc.w + bb.w - mm.w) * rsqrtf(vv.w + EPSBN) * gg.w + be.w;
    o.x = fmaxf(o.x, 0.f); o.y = fmaxf(o.y, 0.f);
    o.z = fmaxf(o.z, 0.f); o.w = fmaxf(o.w, 0.f);
    ((float4*)(out + (size_t)d * 128))[lane] = o;
}

// ---------------- layer-2 GEMM (128 -> 40) fused with attention logits ----------------
__global__ void gemm40(const float* __restrict__ X, const float* __restrict__ W,
                       const float* __restrict__ as2, const float* __restrict__ ad2,
                       float* __restrict__ H2, float* __restrict__ als,
                       float* __restrict__ ald, int n) {
    __shared__ float Ws[NCLASS][129];
    __shared__ float asS[NCLASS], adS[NCLASS];
    __shared__ float xs[8][128];
    int t = threadIdx.x;
    for (int i = t; i < NCLASS * 128; i += blockDim.x) {
        int c = i >> 7, k = i & 127;
        Ws[c][k] = W[i];
    }
    if (t < NCLASS) { asS[t] = as2[t]; adS[t] = ad2[t]; }
    __syncthreads();

    int wid = t >> 5, lane = t & 31;
    int wtotal = (gridDim.x * blockDim.x) >> 5;
    for (int row = blockIdx.x * 8 + wid; row < n; row += wtotal) {
        float4 xv = ((const float4*)(X + (size_t)row * 128))[lane];
        ((float4*)xs[wid])[lane] = xv;
        __syncwarp();
        float acc0 = 0.f, acc1 = 0.f;
        int c0 = lane, c1 = 32 + lane;
#pragma unroll 8
        for (int k = 0; k < 128; k++) {
            float xk = xs[wid][k];
            acc0 += xk * Ws[c0][k];
            if (lane < 8) acc1 += xk * Ws[c1][k];
        }
        H2[(size_t)row * NCLASS + c0] = acc0;
        if (lane < 8) H2[(size_t)row * NCLASS + c1] = acc1;
        float ps = acc0 * asS[c0] + (lane < 8 ? acc1 * asS[c1] : 0.f);
        float pd = acc0 * adS[c0] + (lane < 8 ? acc1 * adS[c1] : 0.f);
        ps = wredsum(ps);
        pd = wredsum(pd);
        if (lane == 0) { als[row] = ps; ald[row] = pd; }
        __syncwarp();
    }
}

// ---------------- fused layer-2 edge stage (1 head) + bias + log_softmax ----------------
__global__ void gat_edge1(const int* __restrict__ rowptr, const int* __restrict__ csrsrc,
                          const float* __restrict__ als, const float* __restrict__ ald,
                          const float* __restrict__ h2, const float* __restrict__ b2,
                          float* __restrict__ out, int n) {
    int lane = threadIdx.x & 31;
    int d = (blockIdx.x * blockDim.x + threadIdx.x) >> 5;
    if (d >= n) return;

    int start = rowptr[d], end = rowptr[d + 1];
    float bld = ald[d];

    float mx = -3.4e38f;
    for (int e = start + lane; e < end; e += 32)
        mx = fmaxf(mx, lrelu(als[csrsrc[e]] + bld));
    mx = wredmax(mx);

    float sm = 0.f;
    for (int e = start + lane; e < end; e += 32)
        sm += __expf(lrelu(als[csrsrc[e]] + bld) - mx);
    sm = wredsum(sm);
    float inv = __frcp_rn(sm);

    float acc0 = 0.f, acc1 = 0.f;
    for (int base = start; base < end; base += 32) {
        int e = base + lane;
        int sv = 0;
        float al = 0.f;
        if (e < end) {
            sv = csrsrc[e];
            al = __expf(lrelu(als[sv] + bld) - mx) * inv;
        }
        int cnt = min(32, end - base);
        for (int j = 0; j < cnt; j++) {
            int   sj = __shfl_sync(0xffffffffu, sv, j);
            float aj = __shfl_sync(0xffffffffu, al, j);
            const float* row = h2 + (size_t)sj * NCLASS;
            acc0 += aj * row[lane];
            if (lane < 8) acc1 += aj * row[32 + lane];
        }
    }

    // bias + log_softmax
    float x0 = acc0 + b2[lane];
    float x1 = (lane < 8) ? acc1 + b2[32 + lane] : -3.4e38f;
    float m = wredmax(fmaxf(x0, x1));
    float s = __expf(x0 - m) + (lane < 8 ? __expf(x1 - m) : 0.f);
    s = wredsum(s);
    float lse = logf(s);
    float* orow = out + (size_t)d * NCLASS;
    orow[lane] = x0 - m - lse;
    if (lane < 8) orow[32 + lane] = x1 - m - lse;
}

// ---------------- host ----------------
extern "C" void kernel_launch(void* const* d_in, const int* in_sizes, int n_in,
                              void* d_out, int out_size) {
    const float* x   = (const float*)d_in[0];
    const int*   ei  = (const int*)d_in[1];
    const float* W0  = (const float*)d_in[2];
    const float* as0 = (const float*)d_in[3];
    const float* ad0 = (const float*)d_in[4];
    const float* b0  = (const float*)d_in[5];
    const float* g0  = (const float*)d_in[6];
    const float* be0 = (const float*)d_in[7];
    const float* m0  = (const float*)d_in[8];
    const float* v0  = (const float*)d_in[9];
    const float* W1  = (const float*)d_in[10];
    const float* as1 = (const float*)d_in[11];
    const float* ad1 = (const float*)d_in[12];
    const float* b1  = (const float*)d_in[13];
    const float* g1  = (const float*)d_in[14];
    const float* be1 = (const float*)d_in[15];
    const float* m1  = (const float*)d_in[16];
    const float* v1  = (const float*)d_in[17];
    const float* W2  = (const float*)d_in[18];
    const float* as2 = (const float*)d_in[19];
    const float* ad2 = (const float*)d_in[20];
    const float* b2  = (const float*)d_in[21];

    int n  = in_sizes[0] / NFEAT;
    int E  = in_sizes[1] / 2;
    int ET = E + n;

    float *h, *agg, *als, *ald;
    int *rowptr, *cnt, *bsum, *csrsrc;
    cudaGetSymbolAddress((void**)&h, g_h);
    cudaGetSymbolAddress((void**)&agg, g_agg);
    cudaGetSymbolAddress((void**)&als, g_als);
    cudaGetSymbolAddress((void**)&ald, g_ald);
    cudaGetSymbolAddress((void**)&rowptr, g_rowptr);
    cudaGetSymbolAddress((void**)&cnt, g_cnt);
    cudaGetSymbolAddress((void**)&bsum, g_bsum);
    cudaGetSymbolAddress((void**)&csrsrc, g_csrsrc);

    const int gb = (n + 127) / 128;          // gemm blocks
    const int ab = (n + 7) / 8;              // warp-per-node blocks (256 thr = 8 warps)
    const int eb = (ET + 255) / 256;         // thread-per-edge blocks
    const int nb = (n + SBS - 1) / SBS;      // scan blocks
    const int cb = (n + 255) / 256;

    // ---------------- CSR build (reused by all 3 layers) ----------------
    zki<<<cb, 256>>>(cnt, n);
    histK<<<eb, 256>>>(ei + E, cnt, E, ET);
    scan1<<<nb, SBS>>>(cnt, rowptr, bsum, n);
    scan2<<<1, SBS>>>(bsum, nb);
    scan3<<<nb, SBS>>>(rowptr, bsum, n);
    zki<<<cb, 256>>>(cnt, n);
    scatterK<<<eb, 256>>>(ei, ei + E, rowptr, cnt, csrsrc, E, ET);

    // ---------------- layer 0 ----------------
    gemm128<<<gb, 256>>>(x, W0, h, n);
    alkern<<<ab, 256>>>(h, as0, ad0, als, ald, n);
    gat_edge4<<<ab, 256>>>(rowptr, csrsrc, als, ald, h, agg, b0, g0, be0, m0, v0, n);

    // ---------------- layer 1 ----------------
    gemm128<<<gb, 256>>>(agg, W1, h, n);
    alkern<<<ab, 256>>>(h, as1, ad1, als, ald, n);
    gat_edge4<<<ab, 256>>>(rowptr, csrsrc, als, ald, h, agg, b1, g1, be1, m1, v1, n);

    // ---------------- layer 2 (heads=1, 40 classes) ----------------
    gemm40<<<1184, 256>>>(agg, W2, as2, ad2, h, als, ald, n);
    gat_edge1<<<ab, 256>>>(rowptr, csrsrc, als, ald, h, b2, (float*)d_out, n);
}

// round 4
// speedup vs baseline: 2.5178x; 1.0707x over previous
#include <cuda_runtime.h>
#include <math.h>

#define NFEAT  128
#define HIDF   128
#define HEADS  4
#define NHID   32
#define NCLASS 40
#define NEGS   0.2f
#define EPSBN  1e-5f
#define MAXN   100000
#define MAXET  1700000   // E (1.6M) + N (100K) self-loops
#define SBS    1024

// ---------------- scratch (static device globals; no allocation) ----------------
__device__ float g_h   [(size_t)MAXN * HIDF];   // projected features (reused as h2 [N,40])
__device__ float g_agg [(size_t)MAXN * HIDF];   // aggregation output / next-layer input
__device__ float g_als [(size_t)MAXN * HEADS];
__device__ float g_ald [(size_t)MAXN * HEADS];
__device__ int   g_rowptr[MAXN + 1];
__device__ int   g_cnt   [MAXN];
__device__ int   g_bsum  [SBS];
__device__ int   g_csrsrc[MAXET];

__device__ __forceinline__ float lrelu(float e) { return e > 0.f ? e : NEGS * e; }

__device__ __forceinline__ float wredmax(float v) {
#pragma unroll
    for (int o = 16; o >= 1; o >>= 1) v = fmaxf(v, __shfl_xor_sync(0xffffffffu, v, o));
    return v;
}
__device__ __forceinline__ float wredsum(float v) {
#pragma unroll
    for (int o = 16; o >= 1; o >>= 1) v += __shfl_xor_sync(0xffffffffu, v, o);
    return v;
}

__device__ __forceinline__ unsigned f2tf(float x) {
    unsigned r;
    asm("cvt.rna.tf32.f32 %0, %1;" : "=r"(r) : "f"(x));
    return r;
}

__device__ __forceinline__ void mma_tf32(float* c, const unsigned* a, const unsigned* b) {
    asm volatile(
        "mma.sync.aligned.m16n8k8.row.col.f32.tf32.tf32.f32 "
        "{%0,%1,%2,%3},{%4,%5,%6,%7},{%8,%9},{%0,%1,%2,%3};"
        : "+f"(c[0]), "+f"(c[1]), "+f"(c[2]), "+f"(c[3])
        : "r"(a[0]), "r"(a[1]), "r"(a[2]), "r"(a[3]), "r"(b[0]), "r"(b[1]));
}

// ---------------- zero fill (ints) ----------------
__global__ void zki(int* __restrict__ p, int cnt) {
    int i = blockIdx.x * blockDim.x + threadIdx.x;
    int stride = gridDim.x * blockDim.x;
    for (; i < cnt; i += stride) p[i] = 0;
}

// ---------------- CSR build ----------------
__global__ void histK(const int* __restrict__ dst, int* __restrict__ hist, int E, int ET) {
    int i = blockIdx.x * blockDim.x + threadIdx.x;
    int stride = gridDim.x * blockDim.x;
    for (; i < ET; i += stride) {
        int d = (i < E) ? dst[i] : (i - E);
        atomicAdd(&hist[d], 1);
    }
}

__global__ void scan1(const int* __restrict__ hist, int* __restrict__ rowptr,
                      int* __restrict__ bsum, int n) {
    __shared__ int tmp[SBS];
    int tid = threadIdx.x;
    int i = blockIdx.x * SBS + tid;
    int val = (i < n) ? hist[i] : 0;
    tmp[tid] = val;
    __syncthreads();
#pragma unroll
    for (int off = 1; off < SBS; off <<= 1) {
        int t2 = (tid >= off) ? tmp[tid - off] : 0;
        __syncthreads();
        tmp[tid] += t2;
        __syncthreads();
    }
    if (i < n) rowptr[i + 1] = tmp[tid];
    if (tid == SBS - 1) bsum[blockIdx.x] = tmp[SBS - 1];
    if (i == 0) rowptr[0] = 0;
}

__global__ void scan2(int* __restrict__ bsum, int nb) {
    __shared__ int tmp[SBS];
    int tid = threadIdx.x;
    int v = (tid < nb) ? bsum[tid] : 0;
    tmp[tid] = v;
    __syncthreads();
#pragma unroll
    for (int off = 1; off < SBS; off <<= 1) {
        int t2 = (tid >= off) ? tmp[tid - off] : 0;
        __syncthreads();
        tmp[tid] += t2;
        __syncthreads();
    }
    if (tid < nb) bsum[tid] = tmp[tid] - v;   // exclusive
}

__global__ void scan3(int* __restrict__ rowptr, const int* __restrict__ bsum, int n) {
    int tid = threadIdx.x;
    int i = blockIdx.x * SBS + tid;
    if (i < n) rowptr[i + 1] += bsum[blockIdx.x];
}

__global__ void scatterK(const int* __restrict__ src, const int* __restrict__ dst,
                         const int* __restrict__ rowptr, int* __restrict__ cnt,
                         int* __restrict__ csrsrc, int E, int ET) {
    int i = blockIdx.x * blockDim.x + threadIdx.x;
    int stride = gridDim.x * blockDim.x;
    for (; i < ET; i += stride) {
        int s, d;
        if (i < E) { s = src[i]; d = dst[i]; } else { s = d = i - E; }
        int pos = rowptr[d] + atomicAdd(&cnt[d], 1);
        csrsrc[pos] = s;
    }
}

// ---------------- tensor-core GEMM (3xTF32): O[n][128] = X[n][128] @ W[128][128]^T ----------------
// 128x128 tile per block, 256 threads (8 warps in 4x2), K-chunks of 16.
#define KC   16
#define KST  20   // smem k-stride (pad for conflict-free fragment LDS)
__global__ void gemm128_tc(const float* __restrict__ X, const float* __restrict__ W,
                           float* __restrict__ O, int n) {
    __shared__ float Ahi[128 * KST], Alo[128 * KST];
    __shared__ float Bhi[128 * KST], Blo[128 * KST];

    int t    = threadIdx.x;
    int lane = t & 31;
    int wid  = t >> 5;
    int wm   = wid >> 1;           // 0..3  -> rows wm*32
    int wn   = wid & 1;            // 0..1  -> cols wn*64
    int gid  = lane >> 2;          // 0..7
    int tig  = lane & 3;           // 0..3
    int row0 = blockIdx.x * 128;

    float acc[2][8][4];
#pragma unroll
    for (int i = 0; i < 2; i++)
#pragma unroll
        for (int j = 0; j < 8; j++)
#pragma unroll
            for (int k = 0; k < 4; k++) acc[i][j][k] = 0.f;

    for (int kt = 0; kt < 128; kt += KC) {
        // load + split X rows and W rows (cols of output) into smem
#pragma unroll
        for (int half = 0; half < 2; half++) {
            int r  = (t >> 2) + half * 64;     // 0..127
            int kq = (t & 3) * 4;              // 0,4,8,12
            int gr = row0 + r;
            float4 xv = (gr < n) ? *(const float4*)(X + (size_t)gr * 128 + kt + kq)
                                 : make_float4(0.f, 0.f, 0.f, 0.f);
            float4 wv = *(const float4*)(W + (size_t)r * 128 + kt + kq);
            float xa[4] = {xv.x, xv.y, xv.z, xv.w};
            float wa[4] = {wv.x, wv.y, wv.z, wv.w};
#pragma unroll
            for (int j = 0; j < 4; j++) {
                unsigned h = f2tf(xa[j]);
                float hf = __uint_as_float(h);
                Ahi[r * KST + kq + j] = hf;
                Alo[r * KST + kq + j] = __uint_as_float(f2tf(xa[j] - hf));
                unsigned hw = f2tf(wa[j]);
                float hwf = __uint_as_float(hw);
                Bhi[r * KST + kq + j] = hwf;
                Blo[r * KST + kq + j] = __uint_as_float(f2tf(wa[j] - hwf));
            }
        }
        __syncthreads();

#pragma unroll
        for (int ks = 0; ks < KC; ks += 8) {
            unsigned ah[2][4], al[2][4];
#pragma unroll
            for (int tm = 0; tm < 2; tm++) {
                int r = wm * 32 + tm * 16 + gid;
                ah[tm][0] = __float_as_uint(Ahi[r * KST + ks + tig]);
                ah[tm][1] = __float_as_uint(Ahi[(r + 8) * KST + ks + tig]);
                ah[tm][2] = __float_as_uint(Ahi[r * KST + ks + tig + 4]);
                ah[tm][3] = __float_as_uint(Ahi[(r + 8) * KST + ks + tig + 4]);
                al[tm][0] = __float_as_uint(Alo[r * KST + ks + tig]);
                al[tm][1] = __float_as_uint(Alo[(r + 8) * KST + ks + tig]);
                al[tm][2] = __float_as_uint(Alo[r * KST + ks + tig + 4]);
                al[tm][3] = __float_as_uint(Alo[(r + 8) * KST + ks + tig + 4]);
            }
            unsigned bh[8][2], bl[8][2];
#pragma unroll
            for (int tn = 0; tn < 8; tn++) {
                int c = wn * 64 + tn * 8 + gid;
                bh[tn][0] = __float_as_uint(Bhi[c * KST + ks + tig]);
                bh[tn][1] = __float_as_uint(Bhi[c * KST + ks + tig + 4]);
                bl[tn][0] = __float_as_uint(Blo[c * KST + ks + tig]);
                bl[tn][1] = __float_as_uint(Blo[c * KST + ks + tig + 4]);
            }
#pragma unroll
            for (int tm = 0; tm < 2; tm++)
#pragma unroll
                for (int tn = 0; tn < 8; tn++) {
                    mma_tf32(acc[tm][tn], ah[tm], bh[tn]);   // hi*hi
                    mma_tf32(acc[tm][tn], ah[tm], bl[tn]);   // hi*lo
                    mma_tf32(acc[tm][tn], al[tm], bh[tn]);   // lo*hi
                }
        }
        __syncthreads();
    }

    // epilogue
#pragma unroll
    for (int tm = 0; tm < 2; tm++) {
        int r = row0 + wm * 32 + tm * 16 + gid;
#pragma unroll
        for (int tn = 0; tn < 8; tn++) {
            int c = wn * 64 + tn * 8 + 2 * tig;
            if (r < n)
                *(float2*)(O + (size_t)r * 128 + c) = make_float2(acc[tm][tn][0], acc[tm][tn][1]);
            if (r + 8 < n)
                *(float2*)(O + (size_t)(r + 8) * 128 + c) = make_float2(acc[tm][tn][2], acc[tm][tn][3]);
        }
    }
}

// ---------------- attention logits: als/ald [n][4] from h [n][128] ----------------
__global__ void alkern(const float* __restrict__ h, const float* __restrict__ as,
                       const float* __restrict__ ad, float* __restrict__ als,
                       float* __restrict__ ald, int n) {
    int lane = threadIdx.x & 31;
    int node = (blockIdx.x * blockDim.x + threadIdx.x) >> 5;
    if (node >= n) return;
    float4 v = ((const float4*)(h + (size_t)node * 128))[lane];
    float4 a = ((const float4*)as)[lane];
    float4 b = ((const float4*)ad)[lane];
    float ps = v.x * a.x + v.y * a.y + v.z * a.z + v.w * a.w;
    float pd = v.x * b.x + v.y * b.y + v.z * b.z + v.w * b.w;
#pragma unroll
    for (int off = 1; off <= 4; off <<= 1) {
        ps += __shfl_xor_sync(0xffffffffu, ps, off);
        pd += __shfl_xor_sync(0xffffffffu, pd, off);
    }
    if ((lane & 7) == 0) {
        int head = lane >> 3;
        als[node * 4 + head] = ps;
        ald[node * 4 + head] = pd;
    }
}

// ---------------- fused GAT edge stage, 4 heads (online softmax + gather + bias/BN/ReLU) ----------------
__global__ void gat_edge4(const int* __restrict__ rowptr, const int* __restrict__ csrsrc,
                          const float* __restrict__ als, const float* __restrict__ ald,
                          const float* __restrict__ h, float* __restrict__ out,
                          const float* __restrict__ bias, const float* __restrict__ gam,
                          const float* __restrict__ bet, const float* __restrict__ mu,
                          const float* __restrict__ var, int n) {
    int lane = threadIdx.x & 31;
    int d = (blockIdx.x * blockDim.x + threadIdx.x) >> 5;
    if (d >= n) return;

    int start = rowptr[d], end = rowptr[d + 1];
    float4 bld = ((const float4*)ald)[d];

    // single-pass online softmax stats per head
    float m0 = -3.4e38f, m1 = -3.4e38f, m2 = -3.4e38f, m3 = -3.4e38f;
    float s0 = 0.f, s1 = 0.f, s2 = 0.f, s3 = 0.f;
    for (int e = start + lane; e < end; e += 32) {
        int s = csrsrc[e];
        float4 a = ((const float4*)als)[s];
        float t0 = lrelu(a.x + bld.x), t1 = lrelu(a.y + bld.y);
        float t2 = lrelu(a.z + bld.z), t3 = lrelu(a.w + bld.w);
        float nm;
        nm = fmaxf(m0, t0); s0 = s0 * __expf(m0 - nm) + __expf(t0 - nm); m0 = nm;
        nm = fmaxf(m1, t1); s1 = s1 * __expf(m1 - nm) + __expf(t1 - nm); m1 = nm;
        nm = fmaxf(m2, t2); s2 = s2 * __expf(m2 - nm) + __expf(t2 - nm); m2 = nm;
        nm = fmaxf(m3, t3); s3 = s3 * __expf(m3 - nm) + __expf(t3 - nm); m3 = nm;
    }
    float g0 = wredmax(m0), g1 = wredmax(m1), g2 = wredmax(m2), g3 = wredmax(m3);
    s0 = wredsum(s0 * __expf(m0 - g0));
    s1 = wredsum(s1 * __expf(m1 - g1));
    s2 = wredsum(s2 * __expf(m2 - g2));
    s3 = wredsum(s3 * __expf(m3 - g3));
    m0 = g0; m1 = g1; m2 = g2; m3 = g3;
    float i0 = __frcp_rn(s0), i1 = __frcp_rn(s1), i2 = __frcp_rn(s2), i3 = __frcp_rn(s3);

    // weighted gather. lane owns columns [4*lane, 4*lane+4); head = lane>>3
    int head = lane >> 3;
    float4 acc = make_float4(0.f, 0.f, 0.f, 0.f);
    for (int base = start; base < end; base += 32) {
        int e = base + lane;
        int sv = 0;
        float a0 = 0.f, a1 = 0.f, a2 = 0.f, a3 = 0.f;
        if (e < end) {
            sv = csrsrc[e];
            float4 a = ((const float4*)als)[sv];
            a0 = __expf(lrelu(a.x + bld.x) - m0) * i0;
            a1 = __expf(lrelu(a.y + bld.y) - m1) * i1;
            a2 = __expf(lrelu(a.z + bld.z) - m2) * i2;
            a3 = __expf(lrelu(a.w + bld.w) - m3) * i3;
        }
        int cnt = min(32, end - base);
        for (int j = 0; j < cnt; j++) {
            int   sj = __shfl_sync(0xffffffffu, sv, j);
            float b0 = __shfl_sync(0xffffffffu, a0, j);
            float b1 = __shfl_sync(0xffffffffu, a1, j);
            float b2 = __shfl_sync(0xffffffffu, a2, j);
            float b3 = __shfl_sync(0xffffffffu, a3, j);
            float aj = (head == 0) ? b0 : (head == 1) ? b1 : (head == 2) ? b2 : b3;
            float4 hv = ((const float4*)h)[(size_t)sj * 32 + lane];
            acc.x += aj * hv.x; acc.y += aj * hv.y;
            acc.z += aj * hv.z; acc.w += aj * hv.w;
        }
    }

    // epilogue: +bias, BN(eval), ReLU
    float4 bb = ((const float4*)bias)[lane];
    float4 gg = ((const float4*)gam)[lane];
    float4 be = ((const float4*)bet)[lane];
    float4 mm = ((const float4*)mu)[lane];
    float4 vv = ((const float4*)var)[lane];
    float4 o;
    o.x = (acc.x + bb.x - mm.x) * rsqrtf(vv.x + EPSBN) * gg.x + be.x;
    o.y = (acc.y + bb.y - mm.y) * rsqrtf(vv.y + EPSBN) * gg.y + be.y;
    o.z = (acc.z + bb.z - mm.z) * rsqrtf(vv.z + EPSBN) * gg.z + be.z;
    o.w = (acc.w + bb.w - mm.w) * rsqrtf(vv.w + EPSBN) * gg.w + be.w;
    o.x = fmaxf(o.x, 0.f); o.y = fmaxf(o.y, 0.f);
    o.z = fmaxf(o.z, 0.f); o.w = fmaxf(o.w, 0.f);
    ((float4*)(out + (size_t)d * 128))[lane] = o;
}

// ---------------- layer-2 GEMM (128 -> 40) fused with attention logits ----------------
__global__ void gemm40(const float* __restrict__ X, const float* __restrict__ W,
                       const float* __restrict__ as2, const float* __restrict__ ad2,
                       float* __restrict__ H2, float* __restrict__ als,
                       float* __restrict__ ald, int n) {
    __shared__ float Ws[NCLASS][129];
    __shared__ float asS[NCLASS], adS[NCLASS];
    __shared__ float xs[8][128];
    int t = threadIdx.x;
    for (int i = t; i < NCLASS * 128; i += blockDim.x) {
        int c = i >> 7, k = i & 127;
        Ws[c][k] = W[i];
    }
    if (t < NCLASS) { asS[t] = as2[t]; adS[t] = ad2[t]; }
    __syncthreads();

    int wid = t >> 5, lane = t & 31;
    int wtotal = (gridDim.x * blockDim.x) >> 5;
    for (int row = blockIdx.x * 8 + wid; row < n; row += wtotal) {
        float4 xv = ((const float4*)(X + (size_t)row * 128))[lane];
        ((float4*)xs[wid])[lane] = xv;
        __syncwarp();
        float acc0 = 0.f, acc1 = 0.f;
        int c0 = lane, c1 = 32 + lane;
#pragma unroll 8
        for (int k = 0; k < 128; k++) {
            float xk = xs[wid][k];
            acc0 += xk * Ws[c0][k];
            if (lane < 8) acc1 += xk * Ws[c1][k];
        }
        H2[(size_t)row * NCLASS + c0] = acc0;
        if (lane < 8) H2[(size_t)row * NCLASS + c1] = acc1;
        float ps = acc0 * asS[c0] + (lane < 8 ? acc1 * asS[c1] : 0.f);
        float pd = acc0 * adS[c0] + (lane < 8 ? acc1 * adS[c1] : 0.f);
        ps = wredsum(ps);
        pd = wredsum(pd);
        if (lane == 0) { als[row] = ps; ald[row] = pd; }
        __syncwarp();
    }
}

// ---------------- fused layer-2 edge stage (1 head) + bias + log_softmax ----------------
__global__ void gat_edge1(const int* __restrict__ rowptr, const int* __restrict__ csrsrc,
                          const float* __restrict__ als, const float* __restrict__ ald,
                          const float* __restrict__ h2, const float* __restrict__ b2,
                          float* __restrict__ out, int n) {
    int lane = threadIdx.x & 31;
    int d = (blockIdx.x * blockDim.x + threadIdx.x) >> 5;
    if (d >= n) return;

    int start = rowptr[d], end = rowptr[d + 1];
    float bld = ald[d];

    // single-pass online softmax stats
    float mx = -3.4e38f, sm = 0.f;
    for (int e = start + lane; e < end; e += 32) {
        float tv = lrelu(als[csrsrc[e]] + bld);
        float nm = fmaxf(mx, tv);
        sm = sm * __expf(mx - nm) + __expf(tv - nm);
        mx = nm;
    }
    float gm = wredmax(mx);
    sm = wredsum(sm * __expf(mx - gm));
    mx = gm;
    float inv = __frcp_rn(sm);

    float acc0 = 0.f, acc1 = 0.f;
    for (int base = start; base < end; base += 32) {
        int e = base + lane;
        int sv = 0;
        float al = 0.f;
        if (e < end) {
            sv = csrsrc[e];
            al = __expf(lrelu(als[sv] + bld) - mx) * inv;
        }
        int cnt = min(32, end - base);
        for (int j = 0; j < cnt; j++) {
            int   sj = __shfl_sync(0xffffffffu, sv, j);
            float aj = __shfl_sync(0xffffffffu, al, j);
            const float* row = h2 + (size_t)sj * NCLASS;
            acc0 += aj * row[lane];
            if (lane < 8) acc1 += aj * row[32 + lane];
        }
    }

    // bias + log_softmax
    float x0 = acc0 + b2[lane];
    float x1 = (lane < 8) ? acc1 + b2[32 + lane] : -3.4e38f;
    float m = wredmax(fmaxf(x0, x1));
    float s = __expf(x0 - m) + (lane < 8 ? __expf(x1 - m) : 0.f);
    s = wredsum(s);
    float lse = logf(s);
    float* orow = out + (size_t)d * NCLASS;
    orow[lane] = x0 - m - lse;
    if (lane < 8) orow[32 + lane] = x1 - m - lse;
}

// ---------------- host ----------------
extern "C" void kernel_launch(void* const* d_in, const int* in_sizes, int n_in,
                              void* d_out, int out_size) {
    const float* x   = (const float*)d_in[0];
    const int*   ei  = (const int*)d_in[1];
    const float* W0  = (const float*)d_in[2];
    const float* as0 = (const float*)d_in[3];
    const float* ad0 = (const float*)d_in[4];
    const float* b0  = (const float*)d_in[5];
    const float* g0  = (const float*)d_in[6];
    const float* be0 = (const float*)d_in[7];
    const float* m0  = (const float*)d_in[8];
    const float* v0  = (const float*)d_in[9];
    const float* W1  = (const float*)d_in[10];
    const float* as1 = (const float*)d_in[11];
    const float* ad1 = (const float*)d_in[12];
    const float* b1  = (const float*)d_in[13];
    const float* g1  = (const float*)d_in[14];
    const float* be1 = (const float*)d_in[15];
    const float* m1  = (const float*)d_in[16];
    const float* v1  = (const float*)d_in[17];
    const float* W2  = (const float*)d_in[18];
    const float* as2 = (const float*)d_in[19];
    const float* ad2 = (const float*)d_in[20];
    const float* b2  = (const float*)d_in[21];

    int n  = in_sizes[0] / NFEAT;
    int E  = in_sizes[1] / 2;
    int ET = E + n;

    float *h, *agg, *als, *ald;
    int *rowptr, *cnt, *bsum, *csrsrc;
    cudaGetSymbolAddress((void**)&h, g_h);
    cudaGetSymbolAddress((void**)&agg, g_agg);
    cudaGetSymbolAddress((void**)&als, g_als);
    cudaGetSymbolAddress((void**)&ald, g_ald);
    cudaGetSymbolAddress((void**)&rowptr, g_rowptr);
    cudaGetSymbolAddress((void**)&cnt, g_cnt);
    cudaGetSymbolAddress((void**)&bsum, g_bsum);
    cudaGetSymbolAddress((void**)&csrsrc, g_csrsrc);

    const int gb = (n + 127) / 128;          // gemm blocks
    const int ab = (n + 7) / 8;              // warp-per-node blocks (256 thr = 8 warps)
    const int eb = (ET + 255) / 256;         // thread-per-edge blocks
    const int nb = (n + SBS - 1) / SBS;      // scan blocks
    const int cb = (n + 255) / 256;

    // ---------------- CSR build (reused by all 3 layers) ----------------
    zki<<<cb, 256>>>(cnt, n);
    histK<<<eb, 256>>>(ei + E, cnt, E, ET);
    scan1<<<nb, SBS>>>(cnt, rowptr, bsum, n);
    scan2<<<1, SBS>>>(bsum, nb);
    scan3<<<nb, SBS>>>(rowptr, bsum, n);
    zki<<<cb, 256>>>(cnt, n);
    scatterK<<<eb, 256>>>(ei, ei + E, rowptr, cnt, csrsrc, E, ET);

    // ---------------- layer 0 ----------------
    gemm128_tc<<<gb, 256>>>(x, W0, h, n);
    alkern<<<ab, 256>>>(h, as0, ad0, als, ald, n);
    gat_edge4<<<ab, 256>>>(rowptr, csrsrc, als, ald, h, agg, b0, g0, be0, m0, v0, n);

    // ---------------- layer 1 ----------------
    gemm128_tc<<<gb, 256>>>(agg, W1, h, n);
    alkern<<<ab, 256>>>(h, as1, ad1, als, ald, n);
    gat_edge4<<<ab, 256>>>(rowptr, csrsrc, als, ald, h, agg, b1, g1, be1, m1, v1, n);

    // ---------------- layer 2 (heads=1, 40 classes) ----------------
    gemm40<<<1184, 256>>>(agg, W2, as2, ad2, h, als, ald, n);
    gat_edge1<<<ab, 256>>>(rowptr, csrsrc, als, ald, h, b2, (float*)d_out, n);
}

// round 5
// speedup vs baseline: 2.5924x; 1.0296x over previous
#include <cuda_runtime.h>
#include <math.h>

#define NFEAT  128
#define HIDF   128
#define HEADS  4
#define NHID   32
#define NCLASS 40
#define NEGS   0.2f
#define EPSBN  1e-5f
#define MAXN   100000
#define MAXET  1700000   // E (1.6M) + N (100K) self-loops

// ---------------- scratch (static device globals; no allocation) ----------------
__device__ float g_h   [(size_t)MAXN * HIDF];   // projected features (reused as h2 [N,40])
__device__ float g_agg [(size_t)MAXN * HIDF];   // aggregation output / next-layer input
__device__ float g_als [(size_t)MAXN * HEADS];
__device__ float g_ald [(size_t)MAXN * HEADS];
__device__ int   g_rowptr[MAXN + 1];
__device__ int   g_cnt   [MAXN];                // hist buffer / scatter cursor (zeroed at end of call)
__device__ int   g_csrsrc[MAXET];

__device__ __forceinline__ float lrelu(float e) { return e > 0.f ? e : NEGS * e; }

__device__ __forceinline__ float wredmax(float v) {
#pragma unroll
    for (int o = 16; o >= 1; o >>= 1) v = fmaxf(v, __shfl_xor_sync(0xffffffffu, v, o));
    return v;
}
__device__ __forceinline__ float wredsum(float v) {
#pragma unroll
    for (int o = 16; o >= 1; o >>= 1) v += __shfl_xor_sync(0xffffffffu, v, o);
    return v;
}

__device__ __forceinline__ unsigned f2tf(float x) {
    unsigned r;
    asm("cvt.rna.tf32.f32 %0, %1;" : "=r"(r) : "f"(x));
    return r;
}

__device__ __forceinline__ void mma_tf32(float* c, const unsigned* a, const unsigned* b) {
    asm volatile(
        "mma.sync.aligned.m16n8k8.row.col.f32.tf32.tf32.f32 "
        "{%0,%1,%2,%3},{%4,%5,%6,%7},{%8,%9},{%0,%1,%2,%3};"
        : "+f"(c[0]), "+f"(c[1]), "+f"(c[2]), "+f"(c[3])
        : "r"(a[0]), "r"(a[1]), "r"(a[2]), "r"(a[3]), "r"(b[0]), "r"(b[1]));
}

// ---------------- zero fill (ints) ----------------
__global__ void zki(int* __restrict__ p, int cnt) {
    int i = blockIdx.x * blockDim.x + threadIdx.x;
    int stride = gridDim.x * blockDim.x;
    for (; i < cnt; i += stride) p[i] = 0;
}

// ---------------- CSR build (3 kernels) ----------------
__global__ void histK(const int* __restrict__ dst, int* __restrict__ hist, int E, int ET) {
    int i = blockIdx.x * blockDim.x + threadIdx.x;
    int stride = gridDim.x * blockDim.x;
    for (; i < ET; i += stride) {
        int d = (i < E) ? dst[i] : (i - E);
        atomicAdd(&hist[d], 1);
    }
}

// single-block blocked exclusive scan over n elements; writes rowptr[0..n] and
// seeds cnt[i] = rowptr[i] so scatter can atomically bump cnt directly.
__global__ void scanAll(const int* __restrict__ hist, int* __restrict__ rowptr,
                        int* __restrict__ cnt, int n) {
    __shared__ int tsum[1024];
    int t = threadIdx.x;
    int C = (n + 1023) >> 10;
    int b = t * C;
    int e = min(b + C, n);
    int s = 0;
    for (int i = b; i < e; i++) s += hist[i];
    tsum[t] = s;
    __syncthreads();
#pragma unroll
    for (int off = 1; off < 1024; off <<= 1) {
        int t2 = (t >= off) ? tsum[t - off] : 0;
        __syncthreads();
        tsum[t] += t2;
        __syncthreads();
    }
    int run = tsum[t] - s;   // exclusive base
    for (int i = b; i < e; i++) {
        int hv = hist[i];
        rowptr[i] = run;
        cnt[i] = run;        // NOTE: aliases hist; read hv first
        run += hv;
    }
    if (e == n && b < n) rowptr[n] = run;
}

__global__ void scatterK(const int* __restrict__ src, const int* __restrict__ dst,
                         int* __restrict__ cnt, int* __restrict__ csrsrc, int E, int ET) {
    int i = blockIdx.x * blockDim.x + threadIdx.x;
    int stride = gridDim.x * blockDim.x;
    for (; i < ET; i += stride) {
        int s, d;
        if (i < E) { s = src[i]; d = dst[i]; } else { s = d = i - E; }
        int pos = atomicAdd(&cnt[d], 1);
        csrsrc[pos] = s;
    }
}

// ---------------- tensor-core GEMM (3xTF32): O[n][128] = X[n][128] @ W[128][128]^T ----------------
#define KC   16
#define KST  20   // smem k-stride (pad)
__global__ void gemm128_tc(const float* __restrict__ X, const float* __restrict__ W,
                           float* __restrict__ O, int n) {
    __shared__ float Ahi[128 * KST], Alo[128 * KST];
    __shared__ float Bhi[128 * KST], Blo[128 * KST];

    int t    = threadIdx.x;
    int lane = t & 31;
    int wid  = t >> 5;
    int wm   = wid >> 1;
    int wn   = wid & 1;
    int gid  = lane >> 2;
    int tig  = lane & 3;
    int row0 = blockIdx.x * 128;

    float acc[2][8][4];
#pragma unroll
    for (int i = 0; i < 2; i++)
#pragma unroll
        for (int j = 0; j < 8; j++)
#pragma unroll
            for (int k = 0; k < 4; k++) acc[i][j][k] = 0.f;

    for (int kt = 0; kt < 128; kt += KC) {
#pragma unroll
        for (int half = 0; half < 2; half++) {
            int r  = (t >> 2) + half * 64;
            int kq = (t & 3) * 4;
            int gr = row0 + r;
            float4 xv = (gr < n) ? *(const float4*)(X + (size_t)gr * 128 + kt + kq)
                                 : make_float4(0.f, 0.f, 0.f, 0.f);
            float4 wv = *(const float4*)(W + (size_t)r * 128 + kt + kq);
            float xa[4] = {xv.x, xv.y, xv.z, xv.w};
            float wa[4] = {wv.x, wv.y, wv.z, wv.w};
            float xh[4], xl[4], wh[4], wl[4];
#pragma unroll
            for (int j = 0; j < 4; j++) {
                xh[j] = __uint_as_float(f2tf(xa[j]));
                xl[j] = __uint_as_float(f2tf(xa[j] - xh[j]));
                wh[j] = __uint_as_float(f2tf(wa[j]));
                wl[j] = __uint_as_float(f2tf(wa[j] - wh[j]));
            }
            *(float4*)&Ahi[r * KST + kq] = make_float4(xh[0], xh[1], xh[2], xh[3]);
            *(float4*)&Alo[r * KST + kq] = make_float4(xl[0], xl[1], xl[2], xl[3]);
            *(float4*)&Bhi[r * KST + kq] = make_float4(wh[0], wh[1], wh[2], wh[3]);
            *(float4*)&Blo[r * KST + kq] = make_float4(wl[0], wl[1], wl[2], wl[3]);
        }
        __syncthreads();

#pragma unroll
        for (int ks = 0; ks < KC; ks += 8) {
            unsigned ah[2][4], al[2][4];
#pragma unroll
            for (int tm = 0; tm < 2; tm++) {
                int r = wm * 32 + tm * 16 + gid;
                ah[tm][0] = __float_as_uint(Ahi[r * KST + ks + tig]);
                ah[tm][1] = __float_as_uint(Ahi[(r + 8) * KST + ks + tig]);
                ah[tm][2] = __float_as_uint(Ahi[r * KST + ks + tig + 4]);
                ah[tm][3] = __float_as_uint(Ahi[(r + 8) * KST + ks + tig + 4]);
                al[tm][0] = __float_as_uint(Alo[r * KST + ks + tig]);
                al[tm][1] = __float_as_uint(Alo[(r + 8) * KST + ks + tig]);
                al[tm][2] = __float_as_uint(Alo[r * KST + ks + tig + 4]);
                al[tm][3] = __float_as_uint(Alo[(r + 8) * KST + ks + tig + 4]);
            }
            unsigned bh[8][2], bl[8][2];
#pragma unroll
            for (int tn = 0; tn < 8; tn++) {
                int c = wn * 64 + tn * 8 + gid;
                bh[tn][0] = __float_as_uint(Bhi[c * KST + ks + tig]);
                bh[tn][1] = __float_as_uint(Bhi[c * KST + ks + tig + 4]);
                bl[tn][0] = __float_as_uint(Blo[c * KST + ks + tig]);
                bl[tn][1] = __float_as_uint(Blo[c * KST + ks + tig + 4]);
            }
#pragma unroll
            for (int tm = 0; tm < 2; tm++)
#pragma unroll
                for (int tn = 0; tn < 8; tn++) {
                    mma_tf32(acc[tm][tn], ah[tm], bh[tn]);
                    mma_tf32(acc[tm][tn], ah[tm], bl[tn]);
                    mma_tf32(acc[tm][tn], al[tm], bh[tn]);
                }
        }
        __syncthreads();
    }

#pragma unroll
    for (int tm = 0; tm < 2; tm++) {
        int r = row0 + wm * 32 + tm * 16 + gid;
#pragma unroll
        for (int tn = 0; tn < 8; tn++) {
            int c = wn * 64 + tn * 8 + 2 * tig;
            if (r < n)
                *(float2*)(O + (size_t)r * 128 + c) = make_float2(acc[tm][tn][0], acc[tm][tn][1]);
            if (r + 8 < n)
                *(float2*)(O + (size_t)(r + 8) * 128 + c) = make_float2(acc[tm][tn][2], acc[tm][tn][3]);
        }
    }
}

// ---------------- attention logits: als/ald [n][4] from h [n][128] ----------------
__global__ void alkern(const float* __restrict__ h, const float* __restrict__ as,
                       const float* __restrict__ ad, float* __restrict__ als,
                       float* __restrict__ ald, int n) {
    int lane = threadIdx.x & 31;
    int node = (blockIdx.x * blockDim.x + threadIdx.x) >> 5;
    if (node >= n) return;
    float4 v = ((const float4*)(h + (size_t)node * 128))[lane];
    float4 a = ((const float4*)as)[lane];
    float4 b = ((const float4*)ad)[lane];
    float ps = v.x * a.x + v.y * a.y + v.z * a.z + v.w * a.w;
    float pd = v.x * b.x + v.y * b.y + v.z * b.z + v.w * b.w;
#pragma unroll
    for (int off = 1; off <= 4; off <<= 1) {
        ps += __shfl_xor_sync(0xffffffffu, ps, off);
        pd += __shfl_xor_sync(0xffffffffu, pd, off);
    }
    if ((lane & 7) == 0) {
        int head = lane >> 3;
        als[node * 4 + head] = ps;
        ald[node * 4 + head] = pd;
    }
}

// ---------------- fused GAT edge stage, 4 heads (online softmax + direct gather + bias/BN/ReLU) ----------------
__global__ void gat_edge4(const int* __restrict__ rowptr, const int* __restrict__ csrsrc,
                          const float* __restrict__ als, const float* __restrict__ ald,
                          const float* __restrict__ h, float* __restrict__ out,
                          const float* __restrict__ bias, const float* __restrict__ gam,
                          const float* __restrict__ bet, const float* __restrict__ mu,
                          const float* __restrict__ var, int n) {
    int lane = threadIdx.x & 31;
    int d = (blockIdx.x * blockDim.x + threadIdx.x) >> 5;
    if (d >= n) return;

    int start = rowptr[d], end = rowptr[d + 1];
    float4 bld = ((const float4*)ald)[d];

    // phase 1: single-pass online softmax stats per head (lane-strided)
    float m0 = -3.4e38f, m1 = -3.4e38f, m2 = -3.4e38f, m3 = -3.4e38f;
    float s0 = 0.f, s1 = 0.f, s2 = 0.f, s3 = 0.f;
    for (int e = start + lane; e < end; e += 32) {
        int s = csrsrc[e];
        float4 a = ((const float4*)als)[s];
        float t0 = lrelu(a.x + bld.x), t1 = lrelu(a.y + bld.y);
        float t2 = lrelu(a.z + bld.z), t3 = lrelu(a.w + bld.w);
        float nm;
        nm = fmaxf(m0, t0); s0 = s0 * __expf(m0 - nm) + __expf(t0 - nm); m0 = nm;
        nm = fmaxf(m1, t1); s1 = s1 * __expf(m1 - nm) + __expf(t1 - nm); m1 = nm;
        nm = fmaxf(m2, t2); s2 = s2 * __expf(m2 - nm) + __expf(t2 - nm); m2 = nm;
        nm = fmaxf(m3, t3); s3 = s3 * __expf(m3 - nm) + __expf(t3 - nm); m3 = nm;
    }
    float gm0 = wredmax(m0), gm1 = wredmax(m1), gm2 = wredmax(m2), gm3 = wredmax(m3);
    s0 = wredsum(s0 * __expf(m0 - gm0));
    s1 = wredsum(s1 * __expf(m1 - gm1));
    s2 = wredsum(s2 * __expf(m2 - gm2));
    s3 = wredsum(s3 * __expf(m3 - gm3));

    // per-lane head-specific constants. lane owns cols [4*lane,4*lane+4); head = lane>>3
    int head = lane >> 3;
    float mh  = (head == 0) ? gm0 : (head == 1) ? gm1 : (head == 2) ? gm2 : gm3;
    float sh  = (head == 0) ? s0  : (head == 1) ? s1  : (head == 2) ? s2  : s3;
    float bh  = (head == 0) ? bld.x : (head == 1) ? bld.y : (head == 2) ? bld.z : bld.w;
    float ih  = __frcp_rn(sh);

    // phase 2: direct gather — every lane processes every edge (broadcast loads, high MLP)
    float4 acc = make_float4(0.f, 0.f, 0.f, 0.f);
#pragma unroll 4
    for (int e = start; e < end; e++) {
        int s = csrsrc[e];                               // broadcast (same addr all lanes)
        float av = als[(size_t)s * 4 + head];            // broadcast per 8 lanes
        float aj = __expf(lrelu(av + bh) - mh) * ih;
        float4 hv = ((const float4*)h)[(size_t)s * 32 + lane];
        acc.x += aj * hv.x; acc.y += aj * hv.y;
        acc.z += aj * hv.z; acc.w += aj * hv.w;
    }

    // epilogue: +bias, BN(eval), ReLU
    float4 bb = ((const float4*)bias)[lane];
    float4 gg = ((const float4*)gam)[lane];
    float4 be = ((const float4*)bet)[lane];
    float4 mm = ((const float4*)mu)[lane];
    float4 vv = ((const float4*)var)[lane];
    float4 o;
    o.x = (acc.x + bb.x - mm.x) * rsqrtf(vv.x + EPSBN) * gg.x + be.x;
    o.y = (acc.y + bb.y - mm.y) * rsqrtf(vv.y + EPSBN) * gg.y + be.y;
    o.z = (acc.z + bb.z - mm.z) * rsqrtf(vv.z + EPSBN) * gg.z + be.z;
    o.w = (acc.w + bb.w - mm.w) * rsqrtf(vv.w + EPSBN) * gg.w + be.w;
    o.x = fmaxf(o.x, 0.f); o.y = fmaxf(o.y, 0.f);
    o.z = fmaxf(o.z, 0.f); o.w = fmaxf(o.w, 0.f);
    ((float4*)(out + (size_t)d * 128))[lane] = o;
}

// ---------------- layer-2 GEMM (128 -> 40) fused with attention logits ----------------
__global__ void gemm40(const float* __restrict__ X, const float* __restrict__ W,
                       const float* __restrict__ as2, const float* __restrict__ ad2,
                       float* __restrict__ H2, float* __restrict__ als,
                       float* __restrict__ ald, int n) {
    __shared__ float Ws[NCLASS][129];
    __shared__ float asS[NCLASS], adS[NCLASS];
    __shared__ float xs[8][128];
    int t = threadIdx.x;
    for (int i = t; i < NCLASS * 128; i += blockDim.x) {
        int c = i >> 7, k = i & 127;
        Ws[c][k] = W[i];
    }
    if (t < NCLASS) { asS[t] = as2[t]; adS[t] = ad2[t]; }
    __syncthreads();

    int wid = t >> 5, lane = t & 31;
    int wtotal = (gridDim.x * blockDim.x) >> 5;
    for (int row = blockIdx.x * 8 + wid; row < n; row += wtotal) {
        float4 xv = ((const float4*)(X + (size_t)row * 128))[lane];
        ((float4*)xs[wid])[lane] = xv;
        __syncwarp();
        float acc0 = 0.f, acc1 = 0.f;
        int c0 = lane, c1 = 32 + lane;
#pragma unroll 8
        for (int k = 0; k < 128; k++) {
            float xk = xs[wid][k];
            acc0 += xk * Ws[c0][k];
            if (lane < 8) acc1 += xk * Ws[c1][k];
        }
        H2[(size_t)row * NCLASS + c0] = acc0;
        if (lane < 8) H2[(size_t)row * NCLASS + c1] = acc1;
        float ps = acc0 * asS[c0] + (lane < 8 ? acc1 * asS[c1] : 0.f);
        float pd = acc0 * adS[c0] + (lane < 8 ? acc1 * adS[c1] : 0.f);
        ps = wredsum(ps);
        pd = wredsum(pd);
        if (lane == 0) { als[row] = ps; ald[row] = pd; }
        __syncwarp();
    }
}

// ---------------- fused layer-2 edge stage (1 head) + bias + log_softmax ----------------
__global__ void gat_edge1(const int* __restrict__ rowptr, const int* __restrict__ csrsrc,
                          const float* __restrict__ als, const float* __restrict__ ald,
                          const float* __restrict__ h2, const float* __restrict__ b2,
                          float* __restrict__ out, int n) {
    int lane = threadIdx.x & 31;
    int d = (blockIdx.x * blockDim.x + threadIdx.x) >> 5;
    if (d >= n) return;

    int start = rowptr[d], end = rowptr[d + 1];
    float bld = ald[d];

    // single-pass online softmax stats (lane-strided)
    float mx = -3.4e38f, sm = 0.f;
    for (int e = start + lane; e < end; e += 32) {
        float tv = lrelu(als[csrsrc[e]] + bld);
        float nm = fmaxf(mx, tv);
        sm = sm * __expf(mx - nm) + __expf(tv - nm);
        mx = nm;
    }
    float gm = wredmax(mx);
    sm = wredsum(sm * __expf(mx - gm));
    mx = gm;
    float inv = __frcp_rn(sm);

    // direct gather — every lane processes every edge
    float acc0 = 0.f, acc1 = 0.f;
#pragma unroll 4
    for (int e = start; e < end; e++) {
        int s = csrsrc[e];                               // broadcast
        float aj = __expf(lrelu(als[s] + bld) - mx) * inv;
        const float* row = h2 + (size_t)s * NCLASS;
        acc0 += aj * row[lane];
        if (lane < 8) acc1 += aj * row[32 + lane];
    }

    // bias + log_softmax
    float x0 = acc0 + b2[lane];
    float x1 = (lane < 8) ? acc1 + b2[32 + lane] : -3.4e38f;
    float m = wredmax(fmaxf(x0, x1));
    float s = __expf(x0 - m) + (lane < 8 ? __expf(x1 - m) : 0.f);
    s = wredsum(s);
    float lse = logf(s);
    float* orow = out + (size_t)d * NCLASS;
    orow[lane] = x0 - m - lse;
    if (lane < 8) orow[32 + lane] = x1 - m - lse;
}

// ---------------- host ----------------
extern "C" void kernel_launch(void* const* d_in, const int* in_sizes, int n_in,
                              void* d_out, int out_size) {
    const float* x   = (const float*)d_in[0];
    const int*   ei  = (const int*)d_in[1];
    const float* W0  = (const float*)d_in[2];
    const float* as0 = (const float*)d_in[3];
    const float* ad0 = (const float*)d_in[4];
    const float* b0  = (const float*)d_in[5];
    const float* g0  = (const float*)d_in[6];
    const float* be0 = (const float*)d_in[7];
    const float* m0  = (const float*)d_in[8];
    const float* v0  = (const float*)d_in[9];
    const float* W1  = (const float*)d_in[10];
    const float* as1 = (const float*)d_in[11];
    const float* ad1 = (const float*)d_in[12];
    const float* b1  = (const float*)d_in[13];
    const float* g1  = (const float*)d_in[14];
    const float* be1 = (const float*)d_in[15];
    const float* m1  = (const float*)d_in[16];
    const float* v1  = (const float*)d_in[17];
    const float* W2  = (const float*)d_in[18];
    const float* as2 = (const float*)d_in[19];
    const float* ad2 = (const float*)d_in[20];
    const float* b2  = (const float*)d_in[21];

    int n  = in_sizes[0] / NFEAT;
    int E  = in_sizes[1] / 2;
    int ET = E + n;

    float *h, *agg, *als, *ald;
    int *rowptr, *cnt, *csrsrc;
    cudaGetSymbolAddress((void**)&h, g_h);
    cudaGetSymbolAddress((void**)&agg, g_agg);
    cudaGetSymbolAddress((void**)&als, g_als);
    cudaGetSymbolAddress((void**)&ald, g_ald);
    cudaGetSymbolAddress((void**)&rowptr, g_rowptr);
    cudaGetSymbolAddress((void**)&cnt, g_cnt);
    cudaGetSymbolAddress((void**)&csrsrc, g_csrsrc);

    const int gb = (n + 127) / 128;          // gemm blocks
    const int ab = (n + 7) / 8;              // warp-per-node blocks (256 thr = 8 warps)
    const int eb = (ET + 255) / 256;         // thread-per-edge blocks
    const int cb = (n + 255) / 256;

    // ---------------- CSR build (cnt is pre-zeroed: device-global init on call 1,
    // trailing zki on every subsequent call) ----------------
    histK<<<eb, 256>>>(ei + E, cnt, E, ET);               // launch 1
    scanAll<<<1, 1024>>>(cnt, rowptr, cnt, n);            // launch 2 (rowptr + cnt=start)
    scatterK<<<eb, 256>>>(ei, ei + E, cnt, csrsrc, E, ET);// launch 3

    // ---------------- layer 0 ----------------
    gemm128_tc<<<gb, 256>>>(x, W0, h, n);                 // launch 4 (ncu profiles this)
    alkern<<<ab, 256>>>(h, as0, ad0, als, ald, n);
    gat_edge4<<<ab, 256>>>(rowptr, csrsrc, als, ald, h, agg, b0, g0, be0, m0, v0, n);

    // ---------------- layer 1 ----------------
    gemm128_tc<<<gb, 256>>>(agg, W1, h, n);
    alkern<<<ab, 256>>>(h, as1, ad1, als, ald, n);
    gat_edge4<<<ab, 256>>>(rowptr, csrsrc, als, ald, h, agg, b1, g1, be1, m1, v1, n);

    // ---------------- layer 2 (heads=1, 40 classes) ----------------
    gemm40<<<1184, 256>>>(agg, W2, as2, ad2, h, als, ald, n);
    gat_edge1<<<ab, 256>>>(rowptr, csrsrc, als, ald, h, b2, (float*)d_out, n);

    // re-zero cnt for the next call (device globals start zeroed, so call 1 is fine)
    zki<<<cb, 256>>>(cnt, n);
}

// round 6
// speedup vs baseline: 2.7388x; 1.0565x over previous
#include <cuda_runtime.h>
#include <math.h>

#define NFEAT  128
#define HIDF   128
#define HEADS  4
#define NHID   32
#define NCLASS 40
#define NEGS   0.2f
#define EPSBN  1e-5f
#define MAXN   100000
#define MAXET  1700000   // E (1.6M) + N (100K) self-loops

// ---------------- scratch (static device globals; no allocation) ----------------
__device__ float g_h   [(size_t)MAXN * HIDF];   // projected features (reused as h2 [N,40])
__device__ float g_agg [(size_t)MAXN * HIDF];   // aggregation output / next-layer input
__device__ float g_als [(size_t)MAXN * HEADS];
__device__ float g_ald [(size_t)MAXN * HEADS];
__device__ int   g_rowptr[MAXN + 1];
__device__ int   g_cnt   [MAXN];                // hist buffer / scatter cursor (zeroed at end of call)
__device__ int   g_csrsrc[MAXET];

__device__ __forceinline__ float lrelu(float e) { return e > 0.f ? e : NEGS * e; }

__device__ __forceinline__ float wredmax(float v) {
#pragma unroll
    for (int o = 16; o >= 1; o >>= 1) v = fmaxf(v, __shfl_xor_sync(0xffffffffu, v, o));
    return v;
}
__device__ __forceinline__ float wredsum(float v) {
#pragma unroll
    for (int o = 16; o >= 1; o >>= 1) v += __shfl_xor_sync(0xffffffffu, v, o);
    return v;
}

__device__ __forceinline__ unsigned f2tf(float x) {
    unsigned r;
    asm("cvt.rna.tf32.f32 %0, %1;" : "=r"(r) : "f"(x));
    return r;
}

__device__ __forceinline__ void mma_tf32(float* c, const unsigned* a, const unsigned* b) {
    asm volatile(
        "mma.sync.aligned.m16n8k8.row.col.f32.tf32.tf32.f32 "
        "{%0,%1,%2,%3},{%4,%5,%6,%7},{%8,%9},{%0,%1,%2,%3};"
        : "+f"(c[0]), "+f"(c[1]), "+f"(c[2]), "+f"(c[3])
        : "r"(a[0]), "r"(a[1]), "r"(a[2]), "r"(a[3]), "r"(b[0]), "r"(b[1]));
}

// ---------------- zero fill (ints) ----------------
__global__ void zki(int* __restrict__ p, int cnt) {
    int i = blockIdx.x * blockDim.x + threadIdx.x;
    int stride = gridDim.x * blockDim.x;
    for (; i < cnt; i += stride) p[i] = 0;
}

// ---------------- CSR build ----------------
__global__ void histK(const int* __restrict__ dst, int* __restrict__ hist, int E, int ET) {
    int i = blockIdx.x * blockDim.x + threadIdx.x;
    int stride = gridDim.x * blockDim.x;
    for (; i < ET; i += stride) {
        int d = (i < E) ? dst[i] : (i - E);
        atomicAdd(&hist[d], 1);
    }
}

// single-block blocked exclusive scan; writes rowptr[0..n] and seeds cnt[i]=rowptr[i].
__global__ void scanAll(const int* __restrict__ hist, int* __restrict__ rowptr,
                        int* __restrict__ cnt, int n) {
    __shared__ int tsum[1024];
    int t = threadIdx.x;
    int C = (n + 1023) >> 10;
    int b = t * C;
    int e = min(b + C, n);
    int s = 0;
    for (int i = b; i < e; i++) s += hist[i];
    tsum[t] = s;
    __syncthreads();
#pragma unroll
    for (int off = 1; off < 1024; off <<= 1) {
        int t2 = (t >= off) ? tsum[t - off] : 0;
        __syncthreads();
        tsum[t] += t2;
        __syncthreads();
    }
    int run = tsum[t] - s;   // exclusive base
    for (int i = b; i < e; i++) {
        int hv = hist[i];
        rowptr[i] = run;
        cnt[i] = run;        // aliases hist; read hv first
        run += hv;
    }
    if (e == n && b < n) rowptr[n] = run;
}

__global__ void scatterK(const int* __restrict__ src, const int* __restrict__ dst,
                         int* __restrict__ cnt, int* __restrict__ csrsrc, int E, int ET) {
    int i = blockIdx.x * blockDim.x + threadIdx.x;
    int stride = gridDim.x * blockDim.x;
    for (; i < ET; i += stride) {
        int s, d;
        if (i < E) { s = src[i]; d = dst[i]; } else { s = d = i - E; }
        int pos = atomicAdd(&cnt[d], 1);
        csrsrc[pos] = s;
    }
}

// ---------------- tensor-core GEMM (3xTF32): O[n][128] = X[n][128] @ W[128][128]^T ----------------
#define KC   16
#define KST  20
__global__ void __launch_bounds__(256, 2)
gemm128_tc(const float* __restrict__ X, const float* __restrict__ W,
           float* __restrict__ O, int n) {
    __shared__ float Ahi[128 * KST], Alo[128 * KST];
    __shared__ float Bhi[128 * KST], Blo[128 * KST];

    int t    = threadIdx.x;
    int lane = t & 31;
    int wid  = t >> 5;
    int wm   = wid >> 1;
    int wn   = wid & 1;
    int gid  = lane >> 2;
    int tig  = lane & 3;
    int row0 = blockIdx.x * 128;

    float acc[2][8][4];
#pragma unroll
    for (int i = 0; i < 2; i++)
#pragma unroll
        for (int j = 0; j < 8; j++)
#pragma unroll
            for (int k = 0; k < 4; k++) acc[i][j][k] = 0.f;

    for (int kt = 0; kt < 128; kt += KC) {
#pragma unroll
        for (int half = 0; half < 2; half++) {
            int r  = (t >> 2) + half * 64;
            int kq = (t & 3) * 4;
            int gr = row0 + r;
            float4 xv = (gr < n) ? *(const float4*)(X + (size_t)gr * 128 + kt + kq)
                                 : make_float4(0.f, 0.f, 0.f, 0.f);
            float4 wv = *(const float4*)(W + (size_t)r * 128 + kt + kq);
            float xa[4] = {xv.x, xv.y, xv.z, xv.w};
            float wa[4] = {wv.x, wv.y, wv.z, wv.w};
            float xh[4], xl[4], wh[4], wl[4];
#pragma unroll
            for (int j = 0; j < 4; j++) {
                xh[j] = __uint_as_float(f2tf(xa[j]));
                xl[j] = __uint_as_float(f2tf(xa[j] - xh[j]));
                wh[j] = __uint_as_float(f2tf(wa[j]));
                wl[j] = __uint_as_float(f2tf(wa[j] - wh[j]));
            }
            *(float4*)&Ahi[r * KST + kq] = make_float4(xh[0], xh[1], xh[2], xh[3]);
            *(float4*)&Alo[r * KST + kq] = make_float4(xl[0], xl[1], xl[2], xl[3]);
            *(float4*)&Bhi[r * KST + kq] = make_float4(wh[0], wh[1], wh[2], wh[3]);
            *(float4*)&Blo[r * KST + kq] = make_float4(wl[0], wl[1], wl[2], wl[3]);
        }
        __syncthreads();

#pragma unroll
        for (int ks = 0; ks < KC; ks += 8) {
            unsigned ah[2][4], al[2][4];
#pragma unroll
            for (int tm = 0; tm < 2; tm++) {
                int r = wm * 32 + tm * 16 + gid;
                ah[tm][0] = __float_as_uint(Ahi[r * KST + ks + tig]);
                ah[tm][1] = __float_as_uint(Ahi[(r + 8) * KST + ks + tig]);
                ah[tm][2] = __float_as_uint(Ahi[r * KST + ks + tig + 4]);
                ah[tm][3] = __float_as_uint(Ahi[(r + 8) * KST + ks + tig + 4]);
                al[tm][0] = __float_as_uint(Alo[r * KST + ks + tig]);
                al[tm][1] = __float_as_uint(Alo[(r + 8) * KST + ks + tig]);
                al[tm][2] = __float_as_uint(Alo[r * KST + ks + tig + 4]);
                al[tm][3] = __float_as_uint(Alo[(r + 8) * KST + ks + tig + 4]);
            }
            unsigned bh[8][2], bl[8][2];
#pragma unroll
            for (int tn = 0; tn < 8; tn++) {
                int c = wn * 64 + tn * 8 + gid;
                bh[tn][0] = __float_as_uint(Bhi[c * KST + ks + tig]);
                bh[tn][1] = __float_as_uint(Bhi[c * KST + ks + tig + 4]);
                bl[tn][0] = __float_as_uint(Blo[c * KST + ks + tig]);
                bl[tn][1] = __float_as_uint(Blo[c * KST + ks + tig + 4]);
            }
            // term-outer ordering: consecutive MMAs target different accumulators
#pragma unroll
            for (int tm = 0; tm < 2; tm++)
#pragma unroll
                for (int tn = 0; tn < 8; tn++)
                    mma_tf32(acc[tm][tn], ah[tm], bh[tn]);
#pragma unroll
            for (int tm = 0; tm < 2; tm++)
#pragma unroll
                for (int tn = 0; tn < 8; tn++)
                    mma_tf32(acc[tm][tn], ah[tm], bl[tn]);
#pragma unroll
            for (int tm = 0; tm < 2; tm++)
#pragma unroll
                for (int tn = 0; tn < 8; tn++)
                    mma_tf32(acc[tm][tn], al[tm], bh[tn]);
        }
        __syncthreads();
    }

#pragma unroll
    for (int tm = 0; tm < 2; tm++) {
        int r = row0 + wm * 32 + tm * 16 + gid;
#pragma unroll
        for (int tn = 0; tn < 8; tn++) {
            int c = wn * 64 + tn * 8 + 2 * tig;
            if (r < n)
                *(float2*)(O + (size_t)r * 128 + c) = make_float2(acc[tm][tn][0], acc[tm][tn][1]);
            if (r + 8 < n)
                *(float2*)(O + (size_t)(r + 8) * 128 + c) = make_float2(acc[tm][tn][2], acc[tm][tn][3]);
        }
    }
}

// ---------------- attention logits: als/ald [n][4] from h [n][128] ----------------
__global__ void alkern(const float* __restrict__ h, const float* __restrict__ as,
                       const float* __restrict__ ad, float* __restrict__ als,
                       float* __restrict__ ald, int n) {
    int lane = threadIdx.x & 31;
    int node = (blockIdx.x * blockDim.x + threadIdx.x) >> 5;
    if (node >= n) return;
    float4 v = ((const float4*)(h + (size_t)node * 128))[lane];
    float4 a = ((const float4*)as)[lane];
    float4 b = ((const float4*)ad)[lane];
    float ps = v.x * a.x + v.y * a.y + v.z * a.z + v.w * a.w;
    float pd = v.x * b.x + v.y * b.y + v.z * b.z + v.w * b.w;
#pragma unroll
    for (int off = 1; off <= 4; off <<= 1) {
        ps += __shfl_xor_sync(0xffffffffu, ps, off);
        pd += __shfl_xor_sync(0xffffffffu, pd, off);
    }
    if ((lane & 7) == 0) {
        int head = lane >> 3;
        als[node * 4 + head] = ps;
        ald[node * 4 + head] = pd;
    }
}

// ---------------- fused GAT edge stage, 4 heads ----------------
__global__ void gat_edge4(const int* __restrict__ rowptr, const int* __restrict__ csrsrc,
                          const float* __restrict__ als, const float* __restrict__ ald,
                          const float* __restrict__ h, float* __restrict__ out,
                          const float* __restrict__ bias, const float* __restrict__ gam,
                          const float* __restrict__ bet, const float* __restrict__ mu,
                          const float* __restrict__ var, int n) {
    int lane = threadIdx.x & 31;
    int d = (blockIdx.x * blockDim.x + threadIdx.x) >> 5;
    if (d >= n) return;

    int start = rowptr[d], end = rowptr[d + 1];
    float4 bld = ((const float4*)ald)[d];

    // phase 1: online softmax stats per head (lane-strided)
    float m0 = -3.4e38f, m1 = -3.4e38f, m2 = -3.4e38f, m3 = -3.4e38f;
    float s0 = 0.f, s1 = 0.f, s2 = 0.f, s3 = 0.f;
    for (int e = start + lane; e < end; e += 32) {
        int s = csrsrc[e];
        float4 a = ((const float4*)als)[s];
        float t0 = lrelu(a.x + bld.x), t1 = lrelu(a.y + bld.y);
        float t2 = lrelu(a.z + bld.z), t3 = lrelu(a.w + bld.w);
        float nm;
        nm = fmaxf(m0, t0); s0 = s0 * __expf(m0 - nm) + __expf(t0 - nm); m0 = nm;
        nm = fmaxf(m1, t1); s1 = s1 * __expf(m1 - nm) + __expf(t1 - nm); m1 = nm;
        nm = fmaxf(m2, t2); s2 = s2 * __expf(m2 - nm) + __expf(t2 - nm); m2 = nm;
        nm = fmaxf(m3, t3); s3 = s3 * __expf(m3 - nm) + __expf(t3 - nm); m3 = nm;
    }
    float gm0 = wredmax(m0), gm1 = wredmax(m1), gm2 = wredmax(m2), gm3 = wredmax(m3);
    s0 = wredsum(s0 * __expf(m0 - gm0));
    s1 = wredsum(s1 * __expf(m1 - gm1));
    s2 = wredsum(s2 * __expf(m2 - gm2));
    s3 = wredsum(s3 * __expf(m3 - gm3));

    int head = lane >> 3;
    float mh  = (head == 0) ? gm0 : (head == 1) ? gm1 : (head == 2) ? gm2 : gm3;
    float sh  = (head == 0) ? s0  : (head == 1) ? s1  : (head == 2) ? s2  : s3;
    float bh  = (head == 0) ? bld.x : (head == 1) ? bld.y : (head == 2) ? bld.z : bld.w;
    float ih  = __frcp_rn(sh);

    // phase 2: direct gather (broadcast loads, high MLP)
    float4 acc = make_float4(0.f, 0.f, 0.f, 0.f);
#pragma unroll 8
    for (int e = start; e < end; e++) {
        int s = csrsrc[e];
        float av = als[(size_t)s * 4 + head];
        float aj = __expf(lrelu(av + bh) - mh) * ih;
        float4 hv = ((const float4*)h)[(size_t)s * 32 + lane];
        acc.x += aj * hv.x; acc.y += aj * hv.y;
        acc.z += aj * hv.z; acc.w += aj * hv.w;
    }

    // epilogue: +bias, BN(eval), ReLU
    float4 bb = ((const float4*)bias)[lane];
    float4 gg = ((const float4*)gam)[lane];
    float4 be = ((const float4*)bet)[lane];
    float4 mm = ((const float4*)mu)[lane];
    float4 vv = ((const float4*)var)[lane];
    float4 o;
    o.x = (acc.x + bb.x - mm.x) * rsqrtf(vv.x + EPSBN) * gg.x + be.x;
    o.y = (acc.y + bb.y - mm.y) * rsqrtf(vv.y + EPSBN) * gg.y + be.y;
    o.z = (acc.z + bb.z - mm.z) * rsqrtf(vv.z + EPSBN) * gg.z + be.z;
    o.w = (acc.w + bb.w - mm.w) * rsqrtf(vv.w + EPSBN) * gg.w + be.w;
    o.x = fmaxf(o.x, 0.f); o.y = fmaxf(o.y, 0.f);
    o.z = fmaxf(o.z, 0.f); o.w = fmaxf(o.w, 0.f);
    ((float4*)(out + (size_t)d * 128))[lane] = o;
}

// ---------------- layer-2 GEMM (128 -> 40) fused with attention logits ----------------
__global__ void gemm40(const float* __restrict__ X, const float* __restrict__ W,
                       const float* __restrict__ as2, const float* __restrict__ ad2,
                       float* __restrict__ H2, float* __restrict__ als,
                       float* __restrict__ ald, int n) {
    __shared__ float Ws[NCLASS][129];
    __shared__ float asS[NCLASS], adS[NCLASS];
    __shared__ float xs[8][128];
    int t = threadIdx.x;
    for (int i = t; i < NCLASS * 128; i += blockDim.x) {
        int c = i >> 7, k = i & 127;
        Ws[c][k] = W[i];
    }
    if (t < NCLASS) { asS[t] = as2[t]; adS[t] = ad2[t]; }
    __syncthreads();

    int wid = t >> 5, lane = t & 31;
    int wtotal = (gridDim.x * blockDim.x) >> 5;
    for (int row = blockIdx.x * 8 + wid; row < n; row += wtotal) {
        float4 xv = ((const float4*)(X + (size_t)row * 128))[lane];
        ((float4*)xs[wid])[lane] = xv;
        __syncwarp();
        float acc0 = 0.f, acc1 = 0.f;
        int c0 = lane, c1 = 32 + lane;
#pragma unroll 8
        for (int k = 0; k < 128; k++) {
            float xk = xs[wid][k];
            acc0 += xk * Ws[c0][k];
            if (lane < 8) acc1 += xk * Ws[c1][k];
        }
        H2[(size_t)row * NCLASS + c0] = acc0;
        if (lane < 8) H2[(size_t)row * NCLASS + c1] = acc1;
        float ps = acc0 * asS[c0] + (lane < 8 ? acc1 * asS[c1] : 0.f);
        float pd = acc0 * adS[c0] + (lane < 8 ? acc1 * adS[c1] : 0.f);
        ps = wredsum(ps);
        pd = wredsum(pd);
        if (lane == 0) { als[row] = ps; ald[row] = pd; }
        __syncwarp();
    }
}

// ---------------- fused layer-2 edge stage (1 head) + bias + log_softmax ----------------
__global__ void gat_edge1(const int* __restrict__ rowptr, const int* __restrict__ csrsrc,
                          const float* __restrict__ als, const float* __restrict__ ald,
                          const float* __restrict__ h2, const float* __restrict__ b2,
                          float* __restrict__ out, int n) {
    int lane = threadIdx.x & 31;
    int d = (blockIdx.x * blockDim.x + threadIdx.x) >> 5;
    if (d >= n) return;

    int start = rowptr[d], end = rowptr[d + 1];
    float bld = ald[d];

    float mx = -3.4e38f, sm = 0.f;
    for (int e = start + lane; e < end; e += 32) {
        float tv = lrelu(als[csrsrc[e]] + bld);
        float nm = fmaxf(mx, tv);
        sm = sm * __expf(mx - nm) + __expf(tv - nm);
        mx = nm;
    }
    float gm = wredmax(mx);
    sm = wredsum(sm * __expf(mx - gm));
    mx = gm;
    float inv = __frcp_rn(sm);

    float acc0 = 0.f, acc1 = 0.f;
#pragma unroll 8
    for (int e = start; e < end; e++) {
        int s = csrsrc[e];
        float aj = __expf(lrelu(als[s] + bld) - mx) * inv;
        const float* row = h2 + (size_t)s * NCLASS;
        acc0 += aj * row[lane];
        if (lane < 8) acc1 += aj * row[32 + lane];
    }

    float x0 = acc0 + b2[lane];
    float x1 = (lane < 8) ? acc1 + b2[32 + lane] : -3.4e38f;
    float m = wredmax(fmaxf(x0, x1));
    float s = __expf(x0 - m) + (lane < 8 ? __expf(x1 - m) : 0.f);
    s = wredsum(s);
    float lse = logf(s);
    float* orow = out + (size_t)d * NCLASS;
    orow[lane] = x0 - m - lse;
    if (lane < 8) orow[32 + lane] = x1 - m - lse;
}

// ---------------- host ----------------
extern "C" void kernel_launch(void* const* d_in, const int* in_sizes, int n_in,
                              void* d_out, int out_size) {
    const float* x   = (const float*)d_in[0];
    const int*   ei  = (const int*)d_in[1];
    const float* W0  = (const float*)d_in[2];
    const float* as0 = (const float*)d_in[3];
    const float* ad0 = (const float*)d_in[4];
    const float* b0  = (const float*)d_in[5];
    const float* g0  = (const float*)d_in[6];
    const float* be0 = (const float*)d_in[7];
    const float* m0  = (const float*)d_in[8];
    const float* v0  = (const float*)d_in[9];
    const float* W1  = (const float*)d_in[10];
    const float* as1 = (const float*)d_in[11];
    const float* ad1 = (const float*)d_in[12];
    const float* b1  = (const float*)d_in[13];
    const float* g1  = (const float*)d_in[14];
    const float* be1 = (const float*)d_in[15];
    const float* m1  = (const float*)d_in[16];
    const float* v1  = (const float*)d_in[17];
    const float* W2  = (const float*)d_in[18];
    const float* as2 = (const float*)d_in[19];
    const float* ad2 = (const float*)d_in[20];
    const float* b2  = (const float*)d_in[21];

    int n  = in_sizes[0] / NFEAT;
    int E  = in_sizes[1] / 2;
    int ET = E + n;

    float *h, *agg, *als, *ald;
    int *rowptr, *cnt, *csrsrc;
    cudaGetSymbolAddress((void**)&h, g_h);
    cudaGetSymbolAddress((void**)&agg, g_agg);
    cudaGetSymbolAddress((void**)&als, g_als);
    cudaGetSymbolAddress((void**)&ald, g_ald);
    cudaGetSymbolAddress((void**)&rowptr, g_rowptr);
    cudaGetSymbolAddress((void**)&cnt, g_cnt);
    cudaGetSymbolAddress((void**)&csrsrc, g_csrsrc);

    // lazily-created side stream + fork/join events (resources, not device memory)
    static cudaStream_t s2 = 0;
    static cudaEvent_t evFork = 0, evJoin = 0;
    if (!s2) {
        cudaStreamCreateWithFlags(&s2, cudaStreamNonBlocking);
        cudaEventCreateWithFlags(&evFork, cudaEventDisableTiming);
        cudaEventCreateWithFlags(&evJoin, cudaEventDisableTiming);
    }

    const int gb  = (n + 127) / 128;           // gemm blocks
    const int ab  = (n + 7) / 8;               // warp-per-node blocks (256 thr)
    const int ab5 = (n + 15) / 16;             // warp-per-node blocks (512 thr)
    const int eb  = (ET + 255) / 256;          // thread-per-edge blocks
    const int cb  = (n + 255) / 256;

    // ---------------- CSR build on side stream, overlapped with layer-0 GEMM ----------------
    cudaEventRecord(evFork, 0);
    cudaStreamWaitEvent(s2, evFork, 0);
    histK   <<<eb, 256, 0, s2>>>(ei + E, cnt, E, ET);
    scanAll <<<1, 1024, 0, s2>>>(cnt, rowptr, cnt, n);
    scatterK<<<eb, 256, 0, s2>>>(ei, ei + E, cnt, csrsrc, E, ET);
    zki     <<<cb, 256, 0, s2>>>(cnt, n);      // re-zero for next call (globals start zeroed)
    cudaEventRecord(evJoin, s2);

    // ---------------- layer 0 (main stream, runs concurrently with CSR) ----------------
    gemm128_tc<<<gb, 256>>>(x, W0, h, n);
    alkern<<<ab, 256>>>(h, as0, ad0, als, ald, n);
    cudaStreamWaitEvent(0, evJoin, 0);         // need csrsrc/rowptr from here on
    gat_edge4<<<ab5, 512>>>(rowptr, csrsrc, als, ald, h, agg, b0, g0, be0, m0, v0, n);

    // ---------------- layer 1 ----------------
    gemm128_tc<<<gb, 256>>>(agg, W1, h, n);
    alkern<<<ab, 256>>>(h, as1, ad1, als, ald, n);
    gat_edge4<<<ab5, 512>>>(rowptr, csrsrc, als, ald, h, agg, b1, g1, be1, m1, v1, n);

    // ---------------- layer 2 (heads=1, 40 classes) ----------------
    gemm40<<<1184, 256>>>(agg, W2, as2, ad2, h, als, ald, n);
    gat_edge1<<<ab5, 512>>>(rowptr, csrsrc, als, ald, h, b2, (float*)d_out, n);
}

// round 8
// speedup vs baseline: 2.9663x; 1.0831x over previous
#include <cuda_runtime.h>
#include <math.h>

#define NFEAT  128
#define HIDF   128
#define HEADS  4
#define NHID   32
#define NCLASS 40
#define NEGS   0.2f
#define EPSBN  1e-5f
#define MAXN   100000
#define MAXET  1700000   // E (1.6M) + N (100K) self-loops

// ---------------- scratch (static device globals; no allocation) ----------------
__device__ float g_h   [(size_t)MAXN * HIDF];   // projected features (reused as h2 [N,40])
__device__ float g_agg [(size_t)MAXN * HIDF];   // aggregation output / next-layer input
__device__ float g_als [(size_t)MAXN * HEADS];
__device__ float g_ald [(size_t)MAXN * HEADS];
__device__ int   g_rowptr[MAXN + 1];
__device__ int   g_cnt   [MAXN];                // hist buffer / scatter cursor (zeroed at end of call)
__device__ int   g_csrsrc[MAXET];

__device__ __forceinline__ float lrelu(float e) { return e > 0.f ? e : NEGS * e; }

__device__ __forceinline__ float wredmax(float v) {
#pragma unroll
    for (int o = 16; o >= 1; o >>= 1) v = fmaxf(v, __shfl_xor_sync(0xffffffffu, v, o));
    return v;
}
__device__ __forceinline__ float wredsum(float v) {
#pragma unroll
    for (int o = 16; o >= 1; o >>= 1) v += __shfl_xor_sync(0xffffffffu, v, o);
    return v;
}

__device__ __forceinline__ unsigned f2tf(float x) {
    unsigned r;
    asm("cvt.rna.tf32.f32 %0, %1;" : "=r"(r) : "f"(x));
    return r;
}

__device__ __forceinline__ void mma_tf32(float* c, const unsigned* a, const unsigned* b) {
    asm volatile(
        "mma.sync.aligned.m16n8k8.row.col.f32.tf32.tf32.f32 "
        "{%0,%1,%2,%3},{%4,%5,%6,%7},{%8,%9},{%0,%1,%2,%3};"
        : "+f"(c[0]), "+f"(c[1]), "+f"(c[2]), "+f"(c[3])
        : "r"(a[0]), "r"(a[1]), "r"(a[2]), "r"(a[3]), "r"(b[0]), "r"(b[1]));
}

// ---------------- zero fill (ints) ----------------
__global__ void zki(int* __restrict__ p, int cnt) {
    int i = blockIdx.x * blockDim.x + threadIdx.x;
    int stride = gridDim.x * blockDim.x;
    for (; i < cnt; i += stride) p[i] = 0;
}

// ---------------- CSR build ----------------
__global__ void histK(const int* __restrict__ dst, int* __restrict__ hist, int E, int ET) {
    int i = blockIdx.x * blockDim.x + threadIdx.x;
    int stride = gridDim.x * blockDim.x;
    for (; i < ET; i += stride) {
        int d = (i < E) ? dst[i] : (i - E);
        atomicAdd(&hist[d], 1);
    }
}

// single-block blocked exclusive scan; writes rowptr[0..n] and seeds cnt[i]=rowptr[i].
__global__ void scanAll(const int* __restrict__ hist, int* __restrict__ rowptr,
                        int* __restrict__ cnt, int n) {
    __shared__ int tsum[1024];
    int t = threadIdx.x;
    int C = (n + 1023) >> 10;
    int b = t * C;
    int e = min(b + C, n);
    int s = 0;
    for (int i = b; i < e; i++) s += hist[i];
    tsum[t] = s;
    __syncthreads();
#pragma unroll
    for (int off = 1; off < 1024; off <<= 1) {
        int t2 = (t >= off) ? tsum[t - off] : 0;
        __syncthreads();
        tsum[t] += t2;
        __syncthreads();
    }
    int run = tsum[t] - s;   // exclusive base
    for (int i = b; i < e; i++) {
        int hv = hist[i];
        rowptr[i] = run;
        cnt[i] = run;        // aliases hist; read hv first
        run += hv;
    }
    if (e == n && b < n) rowptr[n] = run;
}

__global__ void scatterK(const int* __restrict__ src, const int* __restrict__ dst,
                         int* __restrict__ cnt, int* __restrict__ csrsrc, int E, int ET) {
    int i = blockIdx.x * blockDim.x + threadIdx.x;
    int stride = gridDim.x * blockDim.x;
    for (; i < ET; i += stride) {
        int s, d;
        if (i < E) { s = src[i]; d = dst[i]; } else { s = d = i - E; }
        int pos = atomicAdd(&cnt[d], 1);
        csrsrc[pos] = s;
    }
}

// ---------------- tensor-core GEMM (3xTF32): O[n][128] = X[n][128] @ W[128][128]^T ----------------
#define KC   16
#define KST  20
__global__ void __launch_bounds__(256, 2)
gemm128_tc(const float* __restrict__ X, const float* __restrict__ W,
           float* __restrict__ O, int n) {
    __shared__ float Ahi[128 * KST], Alo[128 * KST];
    __shared__ float Bhi[128 * KST], Blo[128 * KST];

    int t    = threadIdx.x;
    int lane = t & 31;
    int wid  = t >> 5;
    int wm   = wid >> 1;
    int wn   = wid & 1;
    int gid  = lane >> 2;
    int tig  = lane & 3;
    int row0 = blockIdx.x * 128;

    float acc[2][8][4];
#pragma unroll
    for (int i = 0; i < 2; i++)
#pragma unroll
        for (int j = 0; j < 8; j++)
#pragma unroll
            for (int k = 0; k < 4; k++) acc[i][j][k] = 0.f;

    for (int kt = 0; kt < 128; kt += KC) {
#pragma unroll
        for (int half = 0; half < 2; half++) {
            int r  = (t >> 2) + half * 64;
            int kq = (t & 3) * 4;
            int gr = row0 + r;
            float4 xv = (gr < n) ? *(const float4*)(X + (size_t)gr * 128 + kt + kq)
                                 : make_float4(0.f, 0.f, 0.f, 0.f);
            float4 wv = *(const float4*)(W + (size_t)r * 128 + kt + kq);
            float xa[4] = {xv.x, xv.y, xv.z, xv.w};
            float wa[4] = {wv.x, wv.y, wv.z, wv.w};
            float xh[4], xl[4], wh[4], wl[4];
#pragma unroll
            for (int j = 0; j < 4; j++) {
                xh[j] = __uint_as_float(f2tf(xa[j]));
                xl[j] = __uint_as_float(f2tf(xa[j] - xh[j]));
                wh[j] = __uint_as_float(f2tf(wa[j]));
                wl[j] = __uint_as_float(f2tf(wa[j] - wh[j]));
            }
            *(float4*)&Ahi[r * KST + kq] = make_float4(xh[0], xh[1], xh[2], xh[3]);
            *(float4*)&Alo[r * KST + kq] = make_float4(xl[0], xl[1], xl[2], xl[3]);
            *(float4*)&Bhi[r * KST + kq] = make_float4(wh[0], wh[1], wh[2], wh[3]);
            *(float4*)&Blo[r * KST + kq] = make_float4(wl[0], wl[1], wl[2], wl[3]);
        }
        __syncthreads();

#pragma unroll
        for (int ks = 0; ks < KC; ks += 8) {
            unsigned ah[2][4], al[2][4];
#pragma unroll
            for (int tm = 0; tm < 2; tm++) {
                int r = wm * 32 + tm * 16 + gid;
                ah[tm][0] = __float_as_uint(Ahi[r * KST + ks + tig]);
                ah[tm][1] = __float_as_uint(Ahi[(r + 8) * KST + ks + tig]);
                ah[tm][2] = __float_as_uint(Ahi[r * KST + ks + tig + 4]);
                ah[tm][3] = __float_as_uint(Ahi[(r + 8) * KST + ks + tig + 4]);
                al[tm][0] = __float_as_uint(Alo[r * KST + ks + tig]);
                al[tm][1] = __float_as_uint(Alo[(r + 8) * KST + ks + tig]);
                al[tm][2] = __float_as_uint(Alo[r * KST + ks + tig + 4]);
                al[tm][3] = __float_as_uint(Alo[(r + 8) * KST + ks + tig + 4]);
            }
            unsigned bh[8][2], bl[8][2];
#pragma unroll
            for (int tn = 0; tn < 8; tn++) {
                int c = wn * 64 + tn * 8 + gid;
                bh[tn][0] = __float_as_uint(Bhi[c * KST + ks + tig]);
                bh[tn][1] = __float_as_uint(Bhi[c * KST + ks + tig + 4]);
                bl[tn][0] = __float_as_uint(Blo[c * KST + ks + tig]);
                bl[tn][1] = __float_as_uint(Blo[c * KST + ks + tig + 4]);
            }
            // term-outer ordering: consecutive MMAs target different accumulators
#pragma unroll
            for (int tm = 0; tm < 2; tm++)
#pragma unroll
                for (int tn = 0; tn < 8; tn++)
                    mma_tf32(acc[tm][tn], ah[tm], bh[tn]);
#pragma unroll
            for (int tm = 0; tm < 2; tm++)
#pragma unroll
                for (int tn = 0; tn < 8; tn++)
                    mma_tf32(acc[tm][tn], ah[tm], bl[tn]);
#pragma unroll
            for (int tm = 0; tm < 2; tm++)
#pragma unroll
                for (int tn = 0; tn < 8; tn++)
                    mma_tf32(acc[tm][tn], al[tm], bh[tn]);
        }
        __syncthreads();
    }

#pragma unroll
    for (int tm = 0; tm < 2; tm++) {
        int r = row0 + wm * 32 + tm * 16 + gid;
#pragma unroll
        for (int tn = 0; tn < 8; tn++) {
            int c = wn * 64 + tn * 8 + 2 * tig;
            if (r < n)
                *(float2*)(O + (size_t)r * 128 + c) = make_float2(acc[tm][tn][0], acc[tm][tn][1]);
            if (r + 8 < n)
                *(float2*)(O + (size_t)(r + 8) * 128 + c) = make_float2(acc[tm][tn][2], acc[tm][tn][3]);
        }
    }
}

// ---------------- attention logits: als/ald [n][4] from h [n][128] ----------------
__global__ void alkern(const float* __restrict__ h, const float* __restrict__ as,
                       const float* __restrict__ ad, float* __restrict__ als,
                       float* __restrict__ ald, int n) {
    int lane = threadIdx.x & 31;
    int node = (blockIdx.x * blockDim.x + threadIdx.x) >> 5;
    if (node >= n) return;
    float4 v = ((const float4*)(h + (size_t)node * 128))[lane];
    float4 a = ((const float4*)as)[lane];
    float4 b = ((const float4*)ad)[lane];
    float ps = v.x * a.x + v.y * a.y + v.z * a.z + v.w * a.w;
    float pd = v.x * b.x + v.y * b.y + v.z * b.z + v.w * b.w;
#pragma unroll
    for (int off = 1; off <= 4; off <<= 1) {
        ps += __shfl_xor_sync(0xffffffffu, ps, off);
        pd += __shfl_xor_sync(0xffffffffu, pd, off);
    }
    if ((lane & 7) == 0) {
        int head = lane >> 3;
        als[node * 4 + head] = ps;
        ald[node * 4 + head] = pd;
    }
}

// ---------------- fused GAT edge stage, 4 heads — SINGLE PASS ----------------
// alpha = exp(e)/sum(exp(e)) identically (max-subtraction dropped; |e| << 80 by
// construction so exp never overflows). Each lane iterates ALL edges of its dst,
// so its local sum of w is already the complete per-head denominator.
__global__ void gat_edge4(const int* __restrict__ rowptr, const int* __restrict__ csrsrc,
                          const float* __restrict__ als, const float* __restrict__ ald,
                          const float* __restrict__ h, float* __restrict__ out,
                          const float* __restrict__ bias, const float* __restrict__ gam,
                          const float* __restrict__ bet, const float* __restrict__ mu,
                          const float* __restrict__ var, int n) {
    int lane = threadIdx.x & 31;
    int d = (blockIdx.x * blockDim.x + threadIdx.x) >> 5;
    if (d >= n) return;

    int start = rowptr[d], end = rowptr[d + 1];
    float4 bld = ((const float4*)ald)[d];
    int head = lane >> 3;
    float bh = (head == 0) ? bld.x : (head == 1) ? bld.y : (head == 2) ? bld.z : bld.w;

    float4 acc = make_float4(0.f, 0.f, 0.f, 0.f);
    float sw = 0.f;
#pragma unroll 8
    for (int e = start; e < end; e++) {
        int s = csrsrc[e];                       // broadcast (same addr all lanes)
        float av = als[(size_t)s * 4 + head];    // broadcast per 8 lanes
        float w = __expf(lrelu(av + bh));
        sw += w;
        float4 hv = ((const float4*)h)[(size_t)s * 32 + lane];
        acc.x += w * hv.x; acc.y += w * hv.y;
        acc.z += w * hv.z; acc.w += w * hv.w;
    }
    float inv = __frcp_rn(sw);

    // epilogue: normalize, +bias, BN(eval), ReLU
    float4 bb = ((const float4*)bias)[lane];
    float4 gg = ((const float4*)gam)[lane];
    float4 be = ((const float4*)bet)[lane];
    float4 mm = ((const float4*)mu)[lane];
    float4 vv = ((const float4*)var)[lane];
    float4 o;
    o.x = (acc.x * inv + bb.x - mm.x) * rsqrtf(vv.x + EPSBN) * gg.x + be.x;
    o.y = (acc.y * inv + bb.y - mm.y) * rsqrtf(vv.y + EPSBN) * gg.y + be.y;
    o.z = (acc.z * inv + bb.z - mm.z) * rsqrtf(vv.z + EPSBN) * gg.z + be.z;
    o.w = (acc.w * inv + bb.w - mm.w) * rsqrtf(vv.w + EPSBN) * gg.w + be.w;
    o.x = fmaxf(o.x, 0.f); o.y = fmaxf(o.y, 0.f);
    o.z = fmaxf(o.z, 0.f); o.w = fmaxf(o.w, 0.f);
    ((float4*)(out + (size_t)d * 128))[lane] = o;
}

// ---------------- layer-2 GEMM (128 -> 40) fused with attention logits ----------------
__global__ void gemm40(const float* __restrict__ X, const float* __restrict__ W,
                       const float* __restrict__ as2, const float* __restrict__ ad2,
                       float* __restrict__ H2, float* __restrict__ als,
                       float* __restrict__ ald, int n) {
    __shared__ float Ws[NCLASS][129];
    __shared__ float asS[NCLASS], adS[NCLASS];
    __shared__ float xs[8][128];
    int t = threadIdx.x;
    for (int i = t; i < NCLASS * 128; i += blockDim.x) {
        int c = i >> 7, k = i & 127;
        Ws[c][k] = W[i];
    }
    if (t < NCLASS) { asS[t] = as2[t]; adS[t] = ad2[t]; }
    __syncthreads();

    int wid = t >> 5, lane = t & 31;
    int wtotal = (gridDim.x * blockDim.x) >> 5;
    for (int row = blockIdx.x * 8 + wid; row < n; row += wtotal) {
        float4 xv = ((const float4*)(X + (size_t)row * 128))[lane];
        ((float4*)xs[wid])[lane] = xv;
        __syncwarp();
        float acc0 = 0.f, acc1 = 0.f;
        int c0 = lane, c1 = 32 + lane;
#pragma unroll 8
        for (int k = 0; k < 128; k++) {
            float xk = xs[wid][k];
            acc0 += xk * Ws[c0][k];
            if (lane < 8) acc1 += xk * Ws[c1][k];
        }
        H2[(size_t)row * NCLASS + c0] = acc0;
        if (lane < 8) H2[(size_t)row * NCLASS + c1] = acc1;
        float ps = acc0 * asS[c0] + (lane < 8 ? acc1 * asS[c1] : 0.f);
        float pd = acc0 * adS[c0] + (lane < 8 ? acc1 * adS[c1] : 0.f);
        ps = wredsum(ps);
        pd = wredsum(pd);
        if (lane == 0) { als[row] = ps; ald[row] = pd; }
        __syncwarp();
    }
}

// ---------------- fused layer-2 edge stage (1 head) — SINGLE PASS + bias + log_softmax ----------------
__global__ void gat_edge1(const int* __restrict__ rowptr, const int* __restrict__ csrsrc,
                          const float* __restrict__ als, const float* __restrict__ ald,
                          const float* __restrict__ h2, const float* __restrict__ b2,
                          float* __restrict__ out, int n) {
    int lane = threadIdx.x & 31;
    int d = (blockIdx.x * blockDim.x + threadIdx.x) >> 5;
    if (d >= n) return;

    int start = rowptr[d], end = rowptr[d + 1];
    float bld = ald[d];

    float acc0 = 0.f, acc1 = 0.f, sw = 0.f;
#pragma unroll 8
    for (int e = start; e < end; e++) {
        int s = csrsrc[e];                       // broadcast
        float w = __expf(lrelu(als[s] + bld));
        sw += w;
        const float* row = h2 + (size_t)s * NCLASS;
        acc0 += w * row[lane];
        if (lane < 8) acc1 += w * row[32 + lane];
    }
    float inv = __frcp_rn(sw);

    // bias + log_softmax
    float x0 = acc0 * inv + b2[lane];
    float x1 = (lane < 8) ? acc1 * inv + b2[32 + lane] : -3.4e38f;
    float m = wredmax(fmaxf(x0, x1));
    float s = __expf(x0 - m) + (lane < 8 ? __expf(x1 - m) : 0.f);
    s = wredsum(s);
    float lse = logf(s);
    float* orow = out + (size_t)d * NCLASS;
    orow[lane] = x0 - m - lse;
    if (lane < 8) orow[32 + lane] = x1 - m - lse;
}

// ---------------- host ----------------
extern "C" void kernel_launch(void* const* d_in, const int* in_sizes, int n_in,
                              void* d_out, int out_size) {
    const float* x   = (const float*)d_in[0];
    const int*   ei  = (const int*)d_in[1];
    const float* W0  = (const float*)d_in[2];
    const float* as0 = (const float*)d_in[3];
    const float* ad0 = (const float*)d_in[4];
    const float* b0  = (const float*)d_in[5];
    const float* g0  = (const float*)d_in[6];
    const float* be0 = (const float*)d_in[7];
    const float* m0  = (const float*)d_in[8];
    const float* v0  = (const float*)d_in[9];
    const float* W1  = (const float*)d_in[10];
    const float* as1 = (const float*)d_in[11];
    const float* ad1 = (const float*)d_in[12];
    const float* b1  = (const float*)d_in[13];
    const float* g1  = (const float*)d_in[14];
    const float* be1 = (const float*)d_in[15];
    const float* m1  = (const float*)d_in[16];
    const float* v1  = (const float*)d_in[17];
    const float* W2  = (const float*)d_in[18];
    const float* as2 = (const float*)d_in[19];
    const float* ad2 = (const float*)d_in[20];
    const float* b2  = (const float*)d_in[21];

    int n  = in_sizes[0] / NFEAT;
    int E  = in_sizes[1] / 2;
    int ET = E + n;

    float *h, *agg, *als, *ald;
    int *rowptr, *cnt, *csrsrc;
    cudaGetSymbolAddress((void**)&h, g_h);
    cudaGetSymbolAddress((void**)&agg, g_agg);
    cudaGetSymbolAddress((void**)&als, g_als);
    cudaGetSymbolAddress((void**)&ald, g_ald);
    cudaGetSymbolAddress((void**)&rowptr, g_rowptr);
    cudaGetSymbolAddress((void**)&cnt, g_cnt);
    cudaGetSymbolAddress((void**)&csrsrc, g_csrsrc);

    // lazily-created side stream + fork/join events (resources, not device memory)
    static cudaStream_t s2 = 0;
    static cudaEvent_t evFork = 0, evJoin = 0;
    if (!s2) {
        cudaStreamCreateWithFlags(&s2, cudaStreamNonBlocking);
        cudaEventCreateWithFlags(&evFork, cudaEventDisableTiming);
        cudaEventCreateWithFlags(&evJoin, cudaEventDisableTiming);
    }

    const int gb  = (n + 127) / 128;           // gemm blocks
    const int ab  = (n + 7) / 8;               // warp-per-node blocks (256 thr)
    const int ab5 = (n + 15) / 16;             // warp-per-node blocks (512 thr)
    const int eb  = (ET + 255) / 256;          // thread-per-edge blocks
    const int cb  = (n + 255) / 256;

    // ---------------- CSR build on side stream, overlapped with layer-0 GEMM ----------------
    cudaEventRecord(evFork, 0);
    cudaStreamWaitEvent(s2, evFork, 0);
    histK   <<<eb, 256, 0, s2>>>(ei + E, cnt, E, ET);
    scanAll <<<1, 1024, 0, s2>>>(cnt, rowptr, cnt, n);
    scatterK<<<eb, 256, 0, s2>>>(ei, ei + E, cnt, csrsrc, E, ET);
    zki     <<<cb, 256, 0, s2>>>(cnt, n);      // re-zero for next call (globals start zeroed)
    cudaEventRecord(evJoin, s2);

    // ---------------- layer 0 (main stream, runs concurrently with CSR) ----------------
    gemm128_tc<<<gb, 256>>>(x, W0, h, n);
    alkern<<<ab, 256>>>(h, as0, ad0, als, ald, n);
    cudaStreamWaitEvent(0, evJoin, 0);         // need csrsrc/rowptr from here on
    gat_edge4<<<ab5, 512>>>(rowptr, csrsrc, als, ald, h, agg, b0, g0, be0, m0, v0, n);

    // ---------------- layer 1 ----------------
    gemm128_tc<<<gb, 256>>>(agg, W1, h, n);
    alkern<<<ab, 256>>>(h, as1, ad1, als, ald, n);
    gat_edge4<<<ab5, 512>>>(rowptr, csrsrc, als, ald, h, agg, b1, g1, be1, m1, v1, n);

    // ---------------- layer 2 (heads=1, 40 classes) ----------------
    gemm40<<<1184, 256>>>(agg, W2, as2, ad2, h, als, ald, n);
    gat_edge1<<<ab5, 512>>>(rowptr, csrsrc, als, ald, h, b2, (float*)d_out, n);
}